// round 4
// baseline (speedup 1.0000x reference)
#include <cuda_runtime.h>
#include <math.h>

#define N_NODES 100000
#define N_EDGES 800000
#define HD      128            // hidden dim H
#define K1      256            // H + IN
#define FF      512            // 4*H
#define INV_SCALE (1.0f/30.0f)
#define LN_EPS  1e-5f

#define EB 64                  // edges per block
#define NB 32                  // nodes per block

// scatter-sum scratch (static device allocation; no cudaMalloc allowed)
__device__ float g_dh[(size_t)N_NODES * HD];

// ---------------------------------------------------------------------------
// zero the aggregation buffer every launch (output poisoning / replay safety)
// ---------------------------------------------------------------------------
__global__ void zero_dh_kernel() {
    size_t n4 = (size_t)N_NODES * HD / 4;
    float4 z = make_float4(0.f, 0.f, 0.f, 0.f);
    float4* p = reinterpret_cast<float4*>(g_dh);
    for (size_t i = (size_t)blockIdx.x * blockDim.x + threadIdx.x; i < n4;
         i += (size_t)gridDim.x * blockDim.x)
        p[i] = z;
}

// ---------------------------------------------------------------------------
// Fused edge MLP: msg = W3(relu(W2(relu(W1 h_E + b1)) + b2)) + b3
// then atomic scatter-add msg/SCALE into g_dh[src].
// Block: 128 threads (one per output column), EB=64 edges.
// ---------------------------------------------------------------------------
__global__ __launch_bounds__(128)
void edge_mlp_kernel(const float* __restrict__ hE,
                     const int* __restrict__ eidx,   // [2, N_EDGES] int32, row 0 = src
                     const float* __restrict__ W1, const float* __restrict__ b1,
                     const float* __restrict__ W2, const float* __restrict__ b2,
                     const float* __restrict__ W3, const float* __restrict__ b3) {
    __shared__ float s_x[EB][64];     // 16 KB : chunk of h_E (64 of 256 cols)
    __shared__ float s_mid[EB][HD];   // 32 KB : layer intermediates
    int* s_src = reinterpret_cast<int*>(s_x);   // overlaid; used after layer 1

    const int j  = threadIdx.x;       // output column 0..127
    const int e0 = blockIdx.x * EB;

    // ---------------- layer 1 : K=256 in 4 chunks of 64 --------------------
    float acc[EB];
    const float bj1 = b1[j];
#pragma unroll
    for (int m = 0; m < EB; m++) acc[m] = bj1;

    const float4* gE4 = reinterpret_cast<const float4*>(hE);
    for (int c = 0; c < 4; c++) {
        // stage chunk: 64 rows x 16 float4
        float4* sx4 = reinterpret_cast<float4*>(&s_x[0][0]);
#pragma unroll
        for (int r = 0; r < 8; r++) {
            int idx = j + r * 128;            // 0..1023
            int m = idx >> 4;
            int q = idx & 15;
            sx4[idx] = gE4[(size_t)(e0 + m) * 64 + c * 16 + q];
        }
        __syncthreads();
        for (int k = 0; k < 64; k += 4) {
            int kg = c * 64 + k;
            float w0 = W1[(kg + 0) * HD + j];
            float w1 = W1[(kg + 1) * HD + j];
            float w2 = W1[(kg + 2) * HD + j];
            float w3 = W1[(kg + 3) * HD + j];
#pragma unroll
            for (int m = 0; m < EB; m++) {
                float4 x = *reinterpret_cast<const float4*>(&s_x[m][k]);
                acc[m] = fmaf(x.x, w0, acc[m]);
                acc[m] = fmaf(x.y, w1, acc[m]);
                acc[m] = fmaf(x.z, w2, acc[m]);
                acc[m] = fmaf(x.w, w3, acc[m]);
            }
        }
        __syncthreads();
    }
    // relu -> s_mid ; also stash src indices into the (now free) s_x area
#pragma unroll
    for (int m = 0; m < EB; m++) s_mid[m][j] = fmaxf(acc[m], 0.f);
    if (j < EB) s_src[j] = eidx[e0 + j];   // row 0 of edge_idx = src (int32)
    __syncthreads();

    // ---------------- layer 2 : 128 -> 128 ---------------------------------
    const float bj2 = b2[j];
#pragma unroll
    for (int m = 0; m < EB; m++) acc[m] = bj2;
    for (int k = 0; k < HD; k += 4) {
        float w0 = W2[(k + 0) * HD + j];
        float w1 = W2[(k + 1) * HD + j];
        float w2 = W2[(k + 2) * HD + j];
        float w3 = W2[(k + 3) * HD + j];
#pragma unroll
        for (int m = 0; m < EB; m++) {
            float4 x = *reinterpret_cast<const float4*>(&s_mid[m][k]);
            acc[m] = fmaf(x.x, w0, acc[m]);
            acc[m] = fmaf(x.y, w1, acc[m]);
            acc[m] = fmaf(x.z, w2, acc[m]);
            acc[m] = fmaf(x.w, w3, acc[m]);
        }
    }
    __syncthreads();
#pragma unroll
    for (int m = 0; m < EB; m++) s_mid[m][j] = fmaxf(acc[m], 0.f);
    __syncthreads();

    // ---------------- layer 3 : 128 -> 128 ---------------------------------
    const float bj3 = b3[j];
#pragma unroll
    for (int m = 0; m < EB; m++) acc[m] = bj3;
    for (int k = 0; k < HD; k += 4) {
        float w0 = W3[(k + 0) * HD + j];
        float w1 = W3[(k + 1) * HD + j];
        float w2 = W3[(k + 2) * HD + j];
        float w3 = W3[(k + 3) * HD + j];
#pragma unroll
        for (int m = 0; m < EB; m++) {
            float4 x = *reinterpret_cast<const float4*>(&s_mid[m][k]);
            acc[m] = fmaf(x.x, w0, acc[m]);
            acc[m] = fmaf(x.y, w1, acc[m]);
            acc[m] = fmaf(x.z, w2, acc[m]);
            acc[m] = fmaf(x.w, w3, acc[m]);
        }
    }

    // ---------------- scatter-add (pre-scaled) ------------------------------
#pragma unroll
    for (int m = 0; m < EB; m++) {
        int s = s_src[m];
        atomicAdd(&g_dh[(size_t)s * HD + j], acc[m] * INV_SCALE);
    }
}

// ---------------------------------------------------------------------------
// Fused node update: h = LN(h_V + dh); out = LN(h + W_ffn(h))
// Block: 128 threads, NB=32 nodes; FFN hidden (512) processed in 4 chunks.
// ---------------------------------------------------------------------------
__global__ __launch_bounds__(128)
void node_kernel(const float* __restrict__ hV,
                 const float* __restrict__ D1, const float* __restrict__ db1,
                 const float* __restrict__ D2, const float* __restrict__ db2,
                 const float* __restrict__ g1, const float* __restrict__ beta1,
                 const float* __restrict__ g2, const float* __restrict__ beta2,
                 float* __restrict__ out) {
    __shared__ float s_x[NB][HD];   // 16 KB : pre-LN input, later residual
    __shared__ float s_h[NB][HD];   // 16 KB : normalized h
    __shared__ float s_t[NB][HD];   // 16 KB : chunk of FFN hidden
    const int j    = threadIdx.x;
    const int n0   = blockIdx.x * NB;
    const int wid  = j >> 5;
    const int lane = j & 31;

    // x = h_V + dh
#pragma unroll
    for (int m = 0; m < NB; m++)
        s_x[m][j] = hV[(size_t)(n0 + m) * HD + j] + g_dh[(size_t)(n0 + m) * HD + j];
    __syncthreads();

    // ---- LN1: each warp handles 8 rows -------------------------------------
#pragma unroll
    for (int r = 0; r < 8; r++) {
        int m = wid * 8 + r;
        float v0 = s_x[m][lane], v1 = s_x[m][lane + 32];
        float v2 = s_x[m][lane + 64], v3 = s_x[m][lane + 96];
        float s = v0 + v1 + v2 + v3;
        float q = v0 * v0 + v1 * v1 + v2 * v2 + v3 * v3;
#pragma unroll
        for (int o = 16; o; o >>= 1) {
            s += __shfl_xor_sync(0xffffffffu, s, o);
            q += __shfl_xor_sync(0xffffffffu, q, o);
        }
        float mean = s * (1.f / HD);
        float var  = q * (1.f / HD) - mean * mean;
        float rstd = rsqrtf(var + LN_EPS);
        s_h[m][lane]      = (v0 - mean) * rstd * g1[lane]      + beta1[lane];
        s_h[m][lane + 32] = (v1 - mean) * rstd * g1[lane + 32] + beta1[lane + 32];
        s_h[m][lane + 64] = (v2 - mean) * rstd * g1[lane + 64] + beta1[lane + 64];
        s_h[m][lane + 96] = (v3 - mean) * rstd * g1[lane + 96] + beta1[lane + 96];
    }
    __syncthreads();

    // ---- FFN: relu(h @ D1 + db1) @ D2 + db2, hidden chunked 4x128 ----------
    float acc2[NB];
    const float bj2 = db2[j];
#pragma unroll
    for (int m = 0; m < NB; m++) acc2[m] = bj2;

    for (int g = 0; g < 4; g++) {
        const int col = g * HD + j;
        float a1[NB];
        const float bc = db1[col];
#pragma unroll
        for (int m = 0; m < NB; m++) a1[m] = bc;
        for (int k = 0; k < HD; k += 4) {
            float w0 = D1[(k + 0) * FF + col];
            float w1 = D1[(k + 1) * FF + col];
            float w2 = D1[(k + 2) * FF + col];
            float w3 = D1[(k + 3) * FF + col];
#pragma unroll
            for (int m = 0; m < NB; m++) {
                float4 x = *reinterpret_cast<const float4*>(&s_h[m][k]);
                a1[m] = fmaf(x.x, w0, a1[m]);
                a1[m] = fmaf(x.y, w1, a1[m]);
                a1[m] = fmaf(x.z, w2, a1[m]);
                a1[m] = fmaf(x.w, w3, a1[m]);
            }
        }
        __syncthreads();   // previous chunk's layer-2 reads are done
#pragma unroll
        for (int m = 0; m < NB; m++) s_t[m][j] = fmaxf(a1[m], 0.f);
        __syncthreads();
        for (int k = 0; k < HD; k += 4) {
            int kg = g * HD + k;
            float w0 = D2[(kg + 0) * HD + j];
            float w1 = D2[(kg + 1) * HD + j];
            float w2 = D2[(kg + 2) * HD + j];
            float w3 = D2[(kg + 3) * HD + j];
#pragma unroll
            for (int m = 0; m < NB; m++) {
                float4 x = *reinterpret_cast<const float4*>(&s_t[m][k]);
                acc2[m] = fmaf(x.x, w0, acc2[m]);
                acc2[m] = fmaf(x.y, w1, acc2[m]);
                acc2[m] = fmaf(x.z, w2, acc2[m]);
                acc2[m] = fmaf(x.w, w3, acc2[m]);
            }
        }
        __syncthreads();
    }

    // ---- residual + LN2 -----------------------------------------------------
#pragma unroll
    for (int m = 0; m < NB; m++) s_x[m][j] = s_h[m][j] + acc2[m];
    __syncthreads();
#pragma unroll
    for (int r = 0; r < 8; r++) {
        int m = wid * 8 + r;
        float v0 = s_x[m][lane], v1 = s_x[m][lane + 32];
        float v2 = s_x[m][lane + 64], v3 = s_x[m][lane + 96];
        float s = v0 + v1 + v2 + v3;
        float q = v0 * v0 + v1 * v1 + v2 * v2 + v3 * v3;
#pragma unroll
        for (int o = 16; o; o >>= 1) {
            s += __shfl_xor_sync(0xffffffffu, s, o);
            q += __shfl_xor_sync(0xffffffffu, q, o);
        }
        float mean = s * (1.f / HD);
        float var  = q * (1.f / HD) - mean * mean;
        float rstd = rsqrtf(var + LN_EPS);
        float* orow = out + (size_t)(n0 + m) * HD;
        orow[lane]      = (v0 - mean) * rstd * g2[lane]      + beta2[lane];
        orow[lane + 32] = (v1 - mean) * rstd * g2[lane + 32] + beta2[lane + 32];
        orow[lane + 64] = (v2 - mean) * rstd * g2[lane + 64] + beta2[lane + 64];
        orow[lane + 96] = (v3 - mean) * rstd * g2[lane + 96] + beta2[lane + 96];
    }
}

// ---------------------------------------------------------------------------
extern "C" void kernel_launch(void* const* d_in, const int* in_sizes, int n_in,
                              void* d_out, int out_size) {
    const float* hV    = (const float*)d_in[0];
    const float* hE    = (const float*)d_in[1];
    const int*   eidx  = (const int*)d_in[2];    // JAX x64 disabled -> int32
    const float* W1    = (const float*)d_in[3];
    const float* b1    = (const float*)d_in[4];
    const float* W2    = (const float*)d_in[5];
    const float* b2    = (const float*)d_in[6];
    const float* W3    = (const float*)d_in[7];
    const float* b3    = (const float*)d_in[8];
    const float* D1    = (const float*)d_in[9];
    const float* db1   = (const float*)d_in[10];
    const float* D2    = (const float*)d_in[11];
    const float* db2   = (const float*)d_in[12];
    const float* g1    = (const float*)d_in[13];
    const float* beta1 = (const float*)d_in[14];
    const float* g2    = (const float*)d_in[15];
    const float* beta2 = (const float*)d_in[16];
    float*       out   = (float*)d_out;

    zero_dh_kernel<<<1024, 256>>>();
    edge_mlp_kernel<<<N_EDGES / EB, 128>>>(hE, eidx, W1, b1, W2, b2, W3, b3);
    node_kernel<<<N_NODES / NB, 128>>>(hV, D1, db1, D2, db2,
                                       g1, beta1, g2, beta2, out);
}

// round 7
// speedup vs baseline: 2.6405x; 2.6405x over previous
#include <cuda_runtime.h>
#include <cuda_bf16.h>
#include <stdint.h>
#include <math.h>

#define N_NODES 100000
#define N_EDGES 800000
#define HD      128            // hidden dim H
#define K1      256            // H + IN
#define FF      512            // 4*H
#define INV_SCALE (1.0f/30.0f)
#define LN_EPS  1e-5f

#define NB 32                  // nodes per block (node kernel)
#define ET 128                 // edges per tile (edge kernel)
#define N_TILES (N_EDGES / ET) // 6250

// ---------------------------------------------------------------------------
// device globals (no cudaMalloc allowed)
// ---------------------------------------------------------------------------
__device__ float          g_dh[(size_t)N_NODES * HD];
__device__ __nv_bfloat16  g_WT1[HD * K1];   // W1^T  [n=128][k=256] bf16
__device__ __nv_bfloat16  g_WT2[HD * HD];   // W2^T  [128][128] bf16
__device__ __nv_bfloat16  g_WT3[HD * HD];   // W3^T  [128][128] bf16

// ---------------------------------------------------------------------------
// SMEM layout (bytes). Row strides padded for conflict-free ldmatrix:
//   256-col bf16 rows: 512B data + 16B pad = 528B  (33 chunks, odd -> cf)
//   128-col bf16 rows: 256B data + 16B pad = 272B  (17 chunks, odd -> cf)
// ---------------------------------------------------------------------------
#define AS1   528              // A / mid region row stride
#define WS1   528              // W1 row stride (k=256)
#define WS2   272              // W2/W3 row stride (k=128)
#define OFF_A    0             // 128*528 = 67584 (A bf16 / mid bf16 / msg fp32)
#define OFF_W1   67584         // 128*528 = 67584
#define OFF_W2   135168        // 128*272 = 34816
#define OFF_W3   169984        // 128*272 = 34816
#define OFF_B1   204800        // 512
#define OFF_B2   205312        // 512
#define OFF_B3   205824        // 512
#define OFF_SRC  206336        // 512
#define SMEM_TOTAL 206848      // ~202 KB

// ---------------------------------------------------------------------------
// PTX helpers — ONLY non-'a' instructions (ldmatrix / mma.sync / red.global)
// ---------------------------------------------------------------------------
__device__ __forceinline__ uint32_t smem_u32(const void* p) {
    uint32_t a;
    asm("{ .reg .u64 t; cvta.to.shared.u64 t, %1; cvt.u32.u64 %0, t; }" : "=r"(a) : "l"(p));
    return a;
}
__device__ __forceinline__ void ldsm_x4(uint32_t addr, uint32_t& r0, uint32_t& r1,
                                        uint32_t& r2, uint32_t& r3) {
    asm volatile("ldmatrix.sync.aligned.m8n8.x4.shared.b16 {%0,%1,%2,%3}, [%4];"
                 : "=r"(r0), "=r"(r1), "=r"(r2), "=r"(r3) : "r"(addr));
}
__device__ __forceinline__ void ldsm_x2(uint32_t addr, uint32_t& r0, uint32_t& r1) {
    asm volatile("ldmatrix.sync.aligned.m8n8.x2.shared.b16 {%0,%1}, [%2];"
                 : "=r"(r0), "=r"(r1) : "r"(addr));
}
__device__ __forceinline__ void mma_16816(float c[4], uint32_t a0, uint32_t a1,
                                          uint32_t a2, uint32_t a3,
                                          uint32_t b0, uint32_t b1) {
    asm volatile("mma.sync.aligned.m16n8k16.row.col.f32.bf16.bf16.f32 "
                 "{%0,%1,%2,%3}, {%4,%5,%6,%7}, {%8,%9}, {%0,%1,%2,%3};"
                 : "+f"(c[0]), "+f"(c[1]), "+f"(c[2]), "+f"(c[3])
                 : "r"(a0), "r"(a1), "r"(a2), "r"(a3), "r"(b0), "r"(b1));
}
// pack {lo, hi} floats into bf16x2 word (lo in bits [15:0])
__device__ __forceinline__ uint32_t pk2(float lo, float hi) {
    uint32_t r;
    asm("cvt.rn.bf16x2.f32 %0, %1, %2;" : "=r"(r) : "f"(hi), "f"(lo));
    return r;
}
__device__ __forceinline__ void red_add_v4(float* p, float a, float b, float c, float d) {
    asm volatile("red.global.add.v4.f32 [%0], {%1, %2, %3, %4};"
                 :: "l"(p), "f"(a), "f"(b), "f"(c), "f"(d) : "memory");
}

// ---------------------------------------------------------------------------
// One MLP layer on mma.sync: acc[2][8][4] = A[128xK] @ W^T[128xK]^T
// Warp (mw 0..3, nw 0..1): rows 32*mw..+31, cols 64*nw..+63.
// ---------------------------------------------------------------------------
template <int KSTEPS, int ASTRIDE, int WSTRIDE>
__device__ __forceinline__ void mlp_layer(uint32_t sb, int Aoff, int Woff,
                                          int lane, int mw, int nw,
                                          float acc[2][8][4]) {
#pragma unroll
    for (int i = 0; i < 2; i++)
#pragma unroll
        for (int j = 0; j < 8; j++)
#pragma unroll
            for (int q = 0; q < 4; q++) acc[i][j][q] = 0.f;

    const uint32_t aBase = sb + Aoff + (mw * 32 + (lane & 15)) * ASTRIDE + ((lane >> 4) << 4);
    const uint32_t bBase = sb + Woff + (nw * 64 + (lane & 7)) * WSTRIDE + (((lane >> 3) & 1) << 4);

#pragma unroll
    for (int ks = 0; ks < KSTEPS; ks++) {
        const int k0b = ks * 32;           // 16 bf16 = 32 bytes per k-step
        uint32_t a0, a1, a2, a3, a4, a5, a6, a7;
        ldsm_x4(aBase + k0b, a0, a1, a2, a3);
        ldsm_x4(aBase + 16 * ASTRIDE + k0b, a4, a5, a6, a7);
#pragma unroll
        for (int j = 0; j < 8; j++) {
            uint32_t b0, b1;
            ldsm_x2(bBase + j * 8 * WSTRIDE + k0b, b0, b1);
            mma_16816(acc[0][j], a0, a1, a2, a3, b0, b1);
            mma_16816(acc[1][j], a4, a5, a6, a7, b0, b1);
        }
    }
}

// bias + relu -> bf16, write back into the A/mid region (stride AS1)
__device__ __forceinline__ void epi_relu_pack(char* smem, const float* bias,
                                              int lane, int mw, int nw,
                                              float acc[2][8][4]) {
#pragma unroll
    for (int i = 0; i < 2; i++) {
        const int r = mw * 32 + i * 16 + (lane >> 2);
#pragma unroll
        for (int j = 0; j < 8; j++) {
            const int c = nw * 64 + j * 8 + (lane & 3) * 2;
            const float bc0 = bias[c], bc1 = bias[c + 1];
            float f0 = fmaxf(acc[i][j][0] + bc0, 0.f);
            float f1 = fmaxf(acc[i][j][1] + bc1, 0.f);
            float f2 = fmaxf(acc[i][j][2] + bc0, 0.f);
            float f3 = fmaxf(acc[i][j][3] + bc1, 0.f);
            *reinterpret_cast<uint32_t*>(smem + OFF_A + r * AS1 + c * 2)       = pk2(f0, f1);
            *reinterpret_cast<uint32_t*>(smem + OFF_A + (r + 8) * AS1 + c * 2) = pk2(f2, f3);
        }
    }
}

// ---------------------------------------------------------------------------
// prep: transpose + bf16-convert weights
// ---------------------------------------------------------------------------
__global__ void prep_weights_kernel(const float* __restrict__ W1,
                                    const float* __restrict__ W2,
                                    const float* __restrict__ W3) {
    int n = blockIdx.x;            // 0..127 output column
    for (int k = threadIdx.x; k < K1; k += blockDim.x)
        g_WT1[n * K1 + k] = __float2bfloat16(W1[k * HD + n]);
    for (int k = threadIdx.x; k < HD; k += blockDim.x) {
        g_WT2[n * HD + k] = __float2bfloat16(W2[k * HD + n]);
        g_WT3[n * HD + k] = __float2bfloat16(W3[k * HD + n]);
    }
}

__global__ void zero_dh_kernel() {
    size_t n4 = (size_t)N_NODES * HD / 4;
    float4 z = make_float4(0.f, 0.f, 0.f, 0.f);
    float4* p = reinterpret_cast<float4*>(g_dh);
    for (size_t i = (size_t)blockIdx.x * blockDim.x + threadIdx.x; i < n4;
         i += (size_t)gridDim.x * blockDim.x)
        p[i] = z;
}

// ---------------------------------------------------------------------------
// Edge MLP on warp-level bf16 HMMA. Persistent: grid=148, 256 threads.
// msg = W3(relu(W2(relu(W1 h_E + b1)) + b2)) + b3 ; scatter msg/30 -> g_dh
// ---------------------------------------------------------------------------
__global__ void __launch_bounds__(256, 1)
edge_hmma_kernel(const float* __restrict__ hE,
                 const int* __restrict__ eidx,
                 const float* __restrict__ b1,
                 const float* __restrict__ b2,
                 const float* __restrict__ b3) {
    extern __shared__ char smem[];
    const uint32_t sb = smem_u32(smem);
    const int tid  = threadIdx.x;
    const int wid  = tid >> 5;
    const int lane = tid & 31;
    const int mw   = wid & 3;          // M-strip 0..3  (rows 32*mw)
    const int nw   = wid >> 2;         // N-half 0..1   (cols 64*nw)

    // ---- stage weights (bf16 [n][k]) into padded-stride SMEM ---------------
    {
        const uint4* w1g = reinterpret_cast<const uint4*>(g_WT1);  // 128 x 32 chunks
#pragma unroll
        for (int i = 0; i < 16; i++) {
            int idx = i * 256 + tid; int n = idx >> 5, ch = idx & 31;
            *reinterpret_cast<uint4*>(smem + OFF_W1 + n * WS1 + ch * 16) = w1g[n * 32 + ch];
        }
        const uint4* w2g = reinterpret_cast<const uint4*>(g_WT2);  // 128 x 16 chunks
        const uint4* w3g = reinterpret_cast<const uint4*>(g_WT3);
#pragma unroll
        for (int i = 0; i < 8; i++) {
            int idx = i * 256 + tid; int n = idx >> 4, ch = idx & 15;
            *reinterpret_cast<uint4*>(smem + OFF_W2 + n * WS2 + ch * 16) = w2g[n * 16 + ch];
            *reinterpret_cast<uint4*>(smem + OFF_W3 + n * WS2 + ch * 16) = w3g[n * 16 + ch];
        }
        if (tid < 128) {
            ((float*)(smem + OFF_B1))[tid] = b1[tid];
            ((float*)(smem + OFF_B2))[tid] = b2[tid];
            ((float*)(smem + OFF_B3))[tid] = b3[tid];
        }
    }
    __syncthreads();

    const float* bias1 = (const float*)(smem + OFF_B1);
    const float* bias2 = (const float*)(smem + OFF_B2);
    const float* bias3 = (const float*)(smem + OFF_B3);
    int* srcArr = (int*)(smem + OFF_SRC);

    float acc[2][8][4];

    for (int tile = blockIdx.x; tile < N_TILES; tile += gridDim.x) {
        const int e0 = tile * ET;

        // ---- stage A: h_E[e0..e0+127][0..255] fp32 -> bf16 (stride 528) ----
        {
            const float4* gE4 = reinterpret_cast<const float4*>(hE) + (size_t)e0 * 64;
#pragma unroll
            for (int i = 0; i < 16; i++) {
                int idx = i * 256 + tid; int r = idx >> 5, ch = idx & 31;
                float4 fa = gE4[(size_t)r * 64 + ch * 2];
                float4 fb = gE4[(size_t)r * 64 + ch * 2 + 1];
                uint4 u;
                u.x = pk2(fa.x, fa.y); u.y = pk2(fa.z, fa.w);
                u.z = pk2(fb.x, fb.y); u.w = pk2(fb.z, fb.w);
                *reinterpret_cast<uint4*>(smem + OFF_A + r * AS1 + ch * 16) = u;
            }
            if (tid < 128) srcArr[tid] = eidx[e0 + tid];
        }
        __syncthreads();

        // ---- layer 1: K=256 -------------------------------------------------
        mlp_layer<16, AS1, WS1>(sb, OFF_A, OFF_W1, lane, mw, nw, acc);
        __syncthreads();                       // everyone done reading A
        epi_relu_pack(smem, bias1, lane, mw, nw, acc);
        __syncthreads();

        // ---- layer 2: K=128 -------------------------------------------------
        mlp_layer<8, AS1, WS2>(sb, OFF_A, OFF_W2, lane, mw, nw, acc);
        __syncthreads();
        epi_relu_pack(smem, bias2, lane, mw, nw, acc);
        __syncthreads();

        // ---- layer 3: K=128 -------------------------------------------------
        mlp_layer<8, AS1, WS2>(sb, OFF_A, OFF_W3, lane, mw, nw, acc);
        __syncthreads();

        // ---- epilogue 3: (acc + b3)/SCALE as fp32 into A region -------------
#pragma unroll
        for (int i = 0; i < 2; i++) {
            const int r = mw * 32 + i * 16 + (lane >> 2);
#pragma unroll
            for (int j = 0; j < 8; j++) {
                const int c = nw * 64 + j * 8 + (lane & 3) * 2;
                const float bc0 = bias3[c], bc1 = bias3[c + 1];
                float2 lo, hi;
                lo.x = (acc[i][j][0] + bc0) * INV_SCALE;
                lo.y = (acc[i][j][1] + bc1) * INV_SCALE;
                hi.x = (acc[i][j][2] + bc0) * INV_SCALE;
                hi.y = (acc[i][j][3] + bc1) * INV_SCALE;
                *reinterpret_cast<float2*>(smem + OFF_A + r * AS1 + c * 4)       = lo;
                *reinterpret_cast<float2*>(smem + OFF_A + (r + 8) * AS1 + c * 4) = hi;
            }
        }
        __syncthreads();

        // ---- scatter: red.global.add.v4 (2 threads per edge row) ------------
        {
            const int row  = tid >> 1;
            const int half = tid & 1;
            const int src  = srcArr[row];
            float* dst = g_dh + (size_t)src * HD + half * 64;
            const float4* srow = reinterpret_cast<const float4*>(smem + OFF_A + row * AS1 + half * 256);
#pragma unroll
            for (int i = 0; i < 16; i++) {
                float4 v = srow[i];
                red_add_v4(dst + i * 4, v.x, v.y, v.z, v.w);
            }
        }
        __syncthreads();                       // A region free for next tile
    }
}

// ---------------------------------------------------------------------------
// Fused node update: h = LN(h_V + dh); out = LN(h + FFN(h))   (fp32)
// ---------------------------------------------------------------------------
__global__ __launch_bounds__(128)
void node_kernel(const float* __restrict__ hV,
                 const float* __restrict__ D1, const float* __restrict__ db1,
                 const float* __restrict__ D2, const float* __restrict__ db2,
                 const float* __restrict__ g1, const float* __restrict__ beta1,
                 const float* __restrict__ g2, const float* __restrict__ beta2,
                 float* __restrict__ out) {
    __shared__ float s_x[NB][HD];
    __shared__ float s_h[NB][HD];
    __shared__ float s_t[NB][HD];
    const int j    = threadIdx.x;
    const int n0   = blockIdx.x * NB;
    const int wid  = j >> 5;
    const int lane = j & 31;

#pragma unroll
    for (int m = 0; m < NB; m++)
        s_x[m][j] = hV[(size_t)(n0 + m) * HD + j] + g_dh[(size_t)(n0 + m) * HD + j];
    __syncthreads();

#pragma unroll
    for (int r = 0; r < 8; r++) {
        int m = wid * 8 + r;
        float v0 = s_x[m][lane], v1 = s_x[m][lane + 32];
        float v2 = s_x[m][lane + 64], v3 = s_x[m][lane + 96];
        float s = v0 + v1 + v2 + v3;
        float q = v0 * v0 + v1 * v1 + v2 * v2 + v3 * v3;
#pragma unroll
        for (int o = 16; o; o >>= 1) {
            s += __shfl_xor_sync(0xffffffffu, s, o);
            q += __shfl_xor_sync(0xffffffffu, q, o);
        }
        float mean = s * (1.f / HD);
        float var  = q * (1.f / HD) - mean * mean;
        float rstd = rsqrtf(var + LN_EPS);
        s_h[m][lane]      = (v0 - mean) * rstd * g1[lane]      + beta1[lane];
        s_h[m][lane + 32] = (v1 - mean) * rstd * g1[lane + 32] + beta1[lane + 32];
        s_h[m][lane + 64] = (v2 - mean) * rstd * g1[lane + 64] + beta1[lane + 64];
        s_h[m][lane + 96] = (v3 - mean) * rstd * g1[lane + 96] + beta1[lane + 96];
    }
    __syncthreads();

    float acc2[NB];
    const float bj2 = db2[j];
#pragma unroll
    for (int m = 0; m < NB; m++) acc2[m] = bj2;

    for (int g = 0; g < 4; g++) {
        const int col = g * HD + j;
        float a1[NB];
        const float bc = db1[col];
#pragma unroll
        for (int m = 0; m < NB; m++) a1[m] = bc;
        for (int k = 0; k < HD; k += 4) {
            float w0 = D1[(k + 0) * FF + col];
            float w1 = D1[(k + 1) * FF + col];
            float w2 = D1[(k + 2) * FF + col];
            float w3 = D1[(k + 3) * FF + col];
#pragma unroll
            for (int m = 0; m < NB; m++) {
                float4 x = *reinterpret_cast<const float4*>(&s_h[m][k]);
                a1[m] = fmaf(x.x, w0, a1[m]);
                a1[m] = fmaf(x.y, w1, a1[m]);
                a1[m] = fmaf(x.z, w2, a1[m]);
                a1[m] = fmaf(x.w, w3, a1[m]);
            }
        }
        __syncthreads();
#pragma unroll
        for (int m = 0; m < NB; m++) s_t[m][j] = fmaxf(a1[m], 0.f);
        __syncthreads();
        for (int k = 0; k < HD; k += 4) {
            int kg = g * HD + k;
            float w0 = D2[(kg + 0) * HD + j];
            float w1 = D2[(kg + 1) * HD + j];
            float w2 = D2[(kg + 2) * HD + j];
            float w3 = D2[(kg + 3) * HD + j];
#pragma unroll
            for (int m = 0; m < NB; m++) {
                float4 x = *reinterpret_cast<const float4*>(&s_t[m][k]);
                acc2[m] = fmaf(x.x, w0, acc2[m]);
                acc2[m] = fmaf(x.y, w1, acc2[m]);
                acc2[m] = fmaf(x.z, w2, acc2[m]);
                acc2[m] = fmaf(x.w, w3, acc2[m]);
            }
        }
        __syncthreads();
    }

#pragma unroll
    for (int m = 0; m < NB; m++) s_x[m][j] = s_h[m][j] + acc2[m];
    __syncthreads();
#pragma unroll
    for (int r = 0; r < 8; r++) {
        int m = wid * 8 + r;
        float v0 = s_x[m][lane], v1 = s_x[m][lane + 32];
        float v2 = s_x[m][lane + 64], v3 = s_x[m][lane + 96];
        float s = v0 + v1 + v2 + v3;
        float q = v0 * v0 + v1 * v1 + v2 * v2 + v3 * v3;
#pragma unroll
        for (int o = 16; o; o >>= 1) {
            s += __shfl_xor_sync(0xffffffffu, s, o);
            q += __shfl_xor_sync(0xffffffffu, q, o);
        }
        float mean = s * (1.f / HD);
        float var  = q * (1.f / HD) - mean * mean;
        float rstd = rsqrtf(var + LN_EPS);
        float* orow = out + (size_t)(n0 + m) * HD;
        orow[lane]      = (v0 - mean) * rstd * g2[lane]      + beta2[lane];
        orow[lane + 32] = (v1 - mean) * rstd * g2[lane + 32] + beta2[lane + 32];
        orow[lane + 64] = (v2 - mean) * rstd * g2[lane + 64] + beta2[lane + 64];
        orow[lane + 96] = (v3 - mean) * rstd * g2[lane + 96] + beta2[lane + 96];
    }
}

// ---------------------------------------------------------------------------
extern "C" void kernel_launch(void* const* d_in, const int* in_sizes, int n_in,
                              void* d_out, int out_size) {
    const float* hV    = (const float*)d_in[0];
    const float* hE    = (const float*)d_in[1];
    const int*   eidx  = (const int*)d_in[2];    // JAX x64 disabled -> int32
    const float* W1    = (const float*)d_in[3];
    const float* b1    = (const float*)d_in[4];
    const float* W2    = (const float*)d_in[5];
    const float* b2    = (const float*)d_in[6];
    const float* W3    = (const float*)d_in[7];
    const float* b3    = (const float*)d_in[8];
    const float* D1    = (const float*)d_in[9];
    const float* db1   = (const float*)d_in[10];
    const float* D2    = (const float*)d_in[11];
    const float* db2   = (const float*)d_in[12];
    const float* g1    = (const float*)d_in[13];
    const float* beta1 = (const float*)d_in[14];
    const float* g2    = (const float*)d_in[15];
    const float* beta2 = (const float*)d_in[16];
    float*       out   = (float*)d_out;

    static int attr_set = 0;
    if (!attr_set) {
        cudaFuncSetAttribute(edge_hmma_kernel,
                             cudaFuncAttributeMaxDynamicSharedMemorySize, SMEM_TOTAL);
        attr_set = 1;
    }

    prep_weights_kernel<<<128, 256>>>(W1, W2, W3);
    zero_dh_kernel<<<1024, 256>>>();
    edge_hmma_kernel<<<148, 256, SMEM_TOTAL>>>(hE, eidx, b1, b2, b3);
    node_kernel<<<N_NODES / NB, 128>>>(hV, D1, db1, D2, db2,
                                       g1, beta1, g2, beta2, out);
}

// round 8
// speedup vs baseline: 4.1992x; 1.5903x over previous
#include <cuda_runtime.h>
#include <cuda_bf16.h>
#include <stdint.h>
#include <math.h>

#define N_NODES 100000
#define N_EDGES 800000
#define HD      128            // hidden dim H
#define K1      256            // H + IN
#define FF      512            // 4*H
#define INV_SCALE (1.0f/30.0f)
#define LN_EPS  1e-5f

#define ET 128                 // edges per tile (edge kernel)
#define N_TILES (N_EDGES / ET) // 6250
#define NODE_TILES ((N_NODES + 127) / 128)   // 782

// ---------------------------------------------------------------------------
// device globals (no cudaMalloc allowed)
// ---------------------------------------------------------------------------
__device__ float          g_dh[(size_t)N_NODES * HD];
__device__ __nv_bfloat16  g_WT1[HD * K1];   // W1^T  [n=128][k=256] bf16
__device__ __nv_bfloat16  g_WT2[HD * HD];   // W2^T  [128][128] bf16
__device__ __nv_bfloat16  g_WT3[HD * HD];   // W3^T  [128][128] bf16
__device__ __nv_bfloat16  g_D1Th[FF * HD];  // D1^T hi  [512][128]
__device__ __nv_bfloat16  g_D1Tl[FF * HD];  // D1^T lo
__device__ __nv_bfloat16  g_D2Th[HD * FF];  // D2^T hi  [128][512]
__device__ __nv_bfloat16  g_D2Tl[HD * FF];  // D2^T lo

// ---------------------------------------------------------------------------
// EDGE kernel SMEM layout (bytes); strides padded for conflict-free ldmatrix
// ---------------------------------------------------------------------------
#define AS1   528
#define WS1   528
#define WS2   272
#define OFF_A    0
#define OFF_W1   67584
#define OFF_W2   135168
#define OFF_W3   169984
#define OFF_B1   204800
#define OFF_B2   205312
#define OFF_B3   205824
#define OFF_SRC  206336
#define SMEM_TOTAL 206848

// ---------------------------------------------------------------------------
// NODE kernel SMEM layout (bytes); bf16 tiles use stride 272
// ---------------------------------------------------------------------------
#define NS2 272
#define NOFF_XH  0            // h hi   [128][128] bf16  34816
#define NOFF_XL  34816        // h lo
#define NOFF_HH  69632        // hidden hi
#define NOFF_HL  104448       // hidden lo
#define NOFF_W   139264       // weight chunk hi(+0)/lo(+34816) = 69632; reused fp32 stage (128*528)
#define NOFF_DB1 208896       // 512 f
#define NOFF_DB2 210944       // 128 f
#define NOFF_G1  211456
#define NOFF_BE1 211968
#define NOFF_G2  212480
#define NOFF_BE2 212992
#define NOFF_ST  213504       // stats float2 [128][2] = 2048
#define NSMEM_TOTAL 215552

// ---------------------------------------------------------------------------
// PTX helpers — ONLY non-'a' instructions (ldmatrix / mma.sync / red.global)
// ---------------------------------------------------------------------------
__device__ __forceinline__ uint32_t smem_u32(const void* p) {
    uint32_t a;
    asm("{ .reg .u64 t; cvta.to.shared.u64 t, %1; cvt.u32.u64 %0, t; }" : "=r"(a) : "l"(p));
    return a;
}
__device__ __forceinline__ void ldsm_x4(uint32_t addr, uint32_t& r0, uint32_t& r1,
                                        uint32_t& r2, uint32_t& r3) {
    asm volatile("ldmatrix.sync.aligned.m8n8.x4.shared.b16 {%0,%1,%2,%3}, [%4];"
                 : "=r"(r0), "=r"(r1), "=r"(r2), "=r"(r3) : "r"(addr));
}
__device__ __forceinline__ void ldsm_x2(uint32_t addr, uint32_t& r0, uint32_t& r1) {
    asm volatile("ldmatrix.sync.aligned.m8n8.x2.shared.b16 {%0,%1}, [%2];"
                 : "=r"(r0), "=r"(r1) : "r"(addr));
}
__device__ __forceinline__ void mma_16816(float c[4], uint32_t a0, uint32_t a1,
                                          uint32_t a2, uint32_t a3,
                                          uint32_t b0, uint32_t b1) {
    asm volatile("mma.sync.aligned.m16n8k16.row.col.f32.bf16.bf16.f32 "
                 "{%0,%1,%2,%3}, {%4,%5,%6,%7}, {%8,%9}, {%0,%1,%2,%3};"
                 : "+f"(c[0]), "+f"(c[1]), "+f"(c[2]), "+f"(c[3])
                 : "r"(a0), "r"(a1), "r"(a2), "r"(a3), "r"(b0), "r"(b1));
}
// pack: low half = first arg
__device__ __forceinline__ uint32_t pk2(float lo, float hi) {
    uint32_t r;
    asm("cvt.rn.bf16x2.f32 %0, %1, %2;" : "=r"(r) : "f"(hi), "f"(lo));
    return r;
}
__device__ __forceinline__ float bflo(uint32_t u) {
    __nv_bfloat162 t = *reinterpret_cast<__nv_bfloat162*>(&u);
    return __bfloat162float(t.x);
}
__device__ __forceinline__ float bfhi(uint32_t u) {
    __nv_bfloat162 t = *reinterpret_cast<__nv_bfloat162*>(&u);
    return __bfloat162float(t.y);
}
// hi/lo split of a float pair into two bf16x2 words
__device__ __forceinline__ void split2(float a, float b, uint32_t& h, uint32_t& l) {
    h = pk2(a, b);
    l = pk2(a - bflo(h), b - bfhi(h));
}
__device__ __forceinline__ void red_add_v4(float* p, float a, float b, float c, float d) {
    asm volatile("red.global.add.v4.f32 [%0], {%1, %2, %3, %4};"
                 :: "l"(p), "f"(a), "f"(b), "f"(c), "f"(d) : "memory");
}

// ---------------------------------------------------------------------------
// single-bf16 MLP layer (edge kernel): acc = A[128xK] @ W[128xK]^T
// ---------------------------------------------------------------------------
template <int KSTEPS, int ASTRIDE, int WSTRIDE>
__device__ __forceinline__ void mlp_layer(uint32_t sb, int Aoff, int Woff,
                                          int lane, int mw, int nw,
                                          float acc[2][8][4]) {
#pragma unroll
    for (int i = 0; i < 2; i++)
#pragma unroll
        for (int j = 0; j < 8; j++)
#pragma unroll
            for (int q = 0; q < 4; q++) acc[i][j][q] = 0.f;

    const uint32_t aBase = sb + Aoff + (mw * 32 + (lane & 15)) * ASTRIDE + ((lane >> 4) << 4);
    const uint32_t bBase = sb + Woff + (nw * 64 + (lane & 7)) * WSTRIDE + (((lane >> 3) & 1) << 4);

#pragma unroll
    for (int ks = 0; ks < KSTEPS; ks++) {
        const int k0b = ks * 32;
        uint32_t a0, a1, a2, a3, a4, a5, a6, a7;
        ldsm_x4(aBase + k0b, a0, a1, a2, a3);
        ldsm_x4(aBase + 16 * ASTRIDE + k0b, a4, a5, a6, a7);
#pragma unroll
        for (int j = 0; j < 8; j++) {
            uint32_t b0, b1;
            ldsm_x2(bBase + j * 8 * WSTRIDE + k0b, b0, b1);
            mma_16816(acc[0][j], a0, a1, a2, a3, b0, b1);
            mma_16816(acc[1][j], a4, a5, a6, a7, b0, b1);
        }
    }
}

// split (hi/lo) MLP layer (node kernel): acc (+)= Ah@Wh + Ah@Wl + Al@Wh
template <int KSTEPS, bool CLEAR>
__device__ __forceinline__ void mlp_layer_split(uint32_t sb, int AHoff, int ALoff,
                                                int WHoff, int WLoff,
                                                int lane, int mw, int nw,
                                                float acc[2][8][4]) {
    if (CLEAR) {
#pragma unroll
        for (int i = 0; i < 2; i++)
#pragma unroll
            for (int j = 0; j < 8; j++)
#pragma unroll
                for (int q = 0; q < 4; q++) acc[i][j][q] = 0.f;
    }
    const uint32_t rb = (mw * 32 + (lane & 15)) * NS2 + ((lane >> 4) << 4);
    const uint32_t ahB = sb + AHoff + rb;
    const uint32_t alB = sb + ALoff + rb;
    const uint32_t wb = (nw * 64 + (lane & 7)) * NS2 + (((lane >> 3) & 1) << 4);
    const uint32_t whB = sb + WHoff + wb;
    const uint32_t wlB = sb + WLoff + wb;

#pragma unroll
    for (int ks = 0; ks < KSTEPS; ks++) {
        const int k0b = ks * 32;
        uint32_t h0, h1, h2, h3, h4, h5, h6, h7;
        uint32_t l0, l1, l2, l3, l4, l5, l6, l7;
        ldsm_x4(ahB + k0b, h0, h1, h2, h3);
        ldsm_x4(ahB + 16 * NS2 + k0b, h4, h5, h6, h7);
        ldsm_x4(alB + k0b, l0, l1, l2, l3);
        ldsm_x4(alB + 16 * NS2 + k0b, l4, l5, l6, l7);
#pragma unroll
        for (int j = 0; j < 8; j++) {
            uint32_t wh0, wh1, wl0, wl1;
            ldsm_x2(whB + j * 8 * NS2 + k0b, wh0, wh1);
            ldsm_x2(wlB + j * 8 * NS2 + k0b, wl0, wl1);
            mma_16816(acc[0][j], h0, h1, h2, h3, wh0, wh1);
            mma_16816(acc[0][j], h0, h1, h2, h3, wl0, wl1);
            mma_16816(acc[0][j], l0, l1, l2, l3, wh0, wh1);
            mma_16816(acc[1][j], h4, h5, h6, h7, wh0, wh1);
            mma_16816(acc[1][j], h4, h5, h6, h7, wl0, wl1);
            mma_16816(acc[1][j], l4, l5, l6, l7, wh0, wh1);
        }
    }
}

// bias + relu -> bf16, write into edge A/mid region (stride AS1)
__device__ __forceinline__ void epi_relu_pack(char* smem, const float* bias,
                                              int lane, int mw, int nw,
                                              float acc[2][8][4]) {
#pragma unroll
    for (int i = 0; i < 2; i++) {
        const int r = mw * 32 + i * 16 + (lane >> 2);
#pragma unroll
        for (int j = 0; j < 8; j++) {
            const int c = nw * 64 + j * 8 + (lane & 3) * 2;
            const float bc0 = bias[c], bc1 = bias[c + 1];
            float f0 = fmaxf(acc[i][j][0] + bc0, 0.f);
            float f1 = fmaxf(acc[i][j][1] + bc1, 0.f);
            float f2 = fmaxf(acc[i][j][2] + bc0, 0.f);
            float f3 = fmaxf(acc[i][j][3] + bc1, 0.f);
            *reinterpret_cast<uint32_t*>(smem + OFF_A + r * AS1 + c * 2)       = pk2(f0, f1);
            *reinterpret_cast<uint32_t*>(smem + OFF_A + (r + 8) * AS1 + c * 2) = pk2(f2, f3);
        }
    }
}

// ---------------------------------------------------------------------------
// prep: transpose + bf16-convert all weights (edge single, node hi/lo split)
// ---------------------------------------------------------------------------
__global__ void prep_weights_kernel(const float* __restrict__ W1,
                                    const float* __restrict__ W2,
                                    const float* __restrict__ W3,
                                    const float* __restrict__ D1,
                                    const float* __restrict__ D2) {
    int n = blockIdx.x;            // 0..511
    int t = threadIdx.x;           // 128 threads
    // D1^T hi/lo: [512][128]
    {
        float v = D1[t * FF + n];
        __nv_bfloat16 h = __float2bfloat16(v);
        g_D1Th[n * HD + t] = h;
        g_D1Tl[n * HD + t] = __float2bfloat16(v - __bfloat162float(h));
    }
    if (n < HD) {
        for (int k = t; k < K1; k += blockDim.x)
            g_WT1[n * K1 + k] = __float2bfloat16(W1[k * HD + n]);
        for (int k = t; k < HD; k += blockDim.x) {
            g_WT2[n * HD + k] = __float2bfloat16(W2[k * HD + n]);
            g_WT3[n * HD + k] = __float2bfloat16(W3[k * HD + n]);
        }
        // D2^T hi/lo: [128][512]
        for (int k = t; k < FF; k += blockDim.x) {
            float v = D2[k * HD + n];
            __nv_bfloat16 h = __float2bfloat16(v);
            g_D2Th[n * FF + k] = h;
            g_D2Tl[n * FF + k] = __float2bfloat16(v - __bfloat162float(h));
        }
    }
}

__global__ void zero_dh_kernel() {
    size_t n4 = (size_t)N_NODES * HD / 4;
    float4 z = make_float4(0.f, 0.f, 0.f, 0.f);
    float4* p = reinterpret_cast<float4*>(g_dh);
    for (size_t i = (size_t)blockIdx.x * blockDim.x + threadIdx.x; i < n4;
         i += (size_t)gridDim.x * blockDim.x)
        p[i] = z;
}

// ---------------------------------------------------------------------------
// Edge MLP on warp-level bf16 HMMA (unchanged from R7 winner)
// ---------------------------------------------------------------------------
__global__ void __launch_bounds__(256, 1)
edge_hmma_kernel(const float* __restrict__ hE,
                 const int* __restrict__ eidx,
                 const float* __restrict__ b1,
                 const float* __restrict__ b2,
                 const float* __restrict__ b3) {
    extern __shared__ char smem[];
    const uint32_t sb = smem_u32(smem);
    const int tid  = threadIdx.x;
    const int wid  = tid >> 5;
    const int lane = tid & 31;
    const int mw   = wid & 3;
    const int nw   = wid >> 2;

    {
        const uint4* w1g = reinterpret_cast<const uint4*>(g_WT1);
#pragma unroll
        for (int i = 0; i < 16; i++) {
            int idx = i * 256 + tid; int n = idx >> 5, ch = idx & 31;
            *reinterpret_cast<uint4*>(smem + OFF_W1 + n * WS1 + ch * 16) = w1g[n * 32 + ch];
        }
        const uint4* w2g = reinterpret_cast<const uint4*>(g_WT2);
        const uint4* w3g = reinterpret_cast<const uint4*>(g_WT3);
#pragma unroll
        for (int i = 0; i < 8; i++) {
            int idx = i * 256 + tid; int n = idx >> 4, ch = idx & 15;
            *reinterpret_cast<uint4*>(smem + OFF_W2 + n * WS2 + ch * 16) = w2g[n * 16 + ch];
            *reinterpret_cast<uint4*>(smem + OFF_W3 + n * WS2 + ch * 16) = w3g[n * 16 + ch];
        }
        if (tid < 128) {
            ((float*)(smem + OFF_B1))[tid] = b1[tid];
            ((float*)(smem + OFF_B2))[tid] = b2[tid];
            ((float*)(smem + OFF_B3))[tid] = b3[tid];
        }
    }
    __syncthreads();

    const float* bias1 = (const float*)(smem + OFF_B1);
    const float* bias2 = (const float*)(smem + OFF_B2);
    const float* bias3 = (const float*)(smem + OFF_B3);
    int* srcArr = (int*)(smem + OFF_SRC);

    float acc[2][8][4];

    for (int tile = blockIdx.x; tile < N_TILES; tile += gridDim.x) {
        const int e0 = tile * ET;
        {
            const float4* gE4 = reinterpret_cast<const float4*>(hE) + (size_t)e0 * 64;
#pragma unroll
            for (int i = 0; i < 16; i++) {
                int idx = i * 256 + tid; int r = idx >> 5, ch = idx & 31;
                float4 fa = gE4[(size_t)r * 64 + ch * 2];
                float4 fb = gE4[(size_t)r * 64 + ch * 2 + 1];
                uint4 u;
                u.x = pk2(fa.x, fa.y); u.y = pk2(fa.z, fa.w);
                u.z = pk2(fb.x, fb.y); u.w = pk2(fb.z, fb.w);
                *reinterpret_cast<uint4*>(smem + OFF_A + r * AS1 + ch * 16) = u;
            }
            if (tid < 128) srcArr[tid] = eidx[e0 + tid];
        }
        __syncthreads();

        mlp_layer<16, AS1, WS1>(sb, OFF_A, OFF_W1, lane, mw, nw, acc);
        __syncthreads();
        epi_relu_pack(smem, bias1, lane, mw, nw, acc);
        __syncthreads();

        mlp_layer<8, AS1, WS2>(sb, OFF_A, OFF_W2, lane, mw, nw, acc);
        __syncthreads();
        epi_relu_pack(smem, bias2, lane, mw, nw, acc);
        __syncthreads();

        mlp_layer<8, AS1, WS2>(sb, OFF_A, OFF_W3, lane, mw, nw, acc);
        __syncthreads();

#pragma unroll
        for (int i = 0; i < 2; i++) {
            const int r = mw * 32 + i * 16 + (lane >> 2);
#pragma unroll
            for (int j = 0; j < 8; j++) {
                const int c = nw * 64 + j * 8 + (lane & 3) * 2;
                const float bc0 = bias3[c], bc1 = bias3[c + 1];
                float2 lo, hi;
                lo.x = (acc[i][j][0] + bc0) * INV_SCALE;
                lo.y = (acc[i][j][1] + bc1) * INV_SCALE;
                hi.x = (acc[i][j][2] + bc0) * INV_SCALE;
                hi.y = (acc[i][j][3] + bc1) * INV_SCALE;
                *reinterpret_cast<float2*>(smem + OFF_A + r * AS1 + c * 4)       = lo;
                *reinterpret_cast<float2*>(smem + OFF_A + (r + 8) * AS1 + c * 4) = hi;
            }
        }
        __syncthreads();

        {
            const int row  = tid >> 1;
            const int half = tid & 1;
            const int src  = srcArr[row];
            float* dst = g_dh + (size_t)src * HD + half * 64;
            const float4* srow = reinterpret_cast<const float4*>(smem + OFF_A + row * AS1 + half * 256);
#pragma unroll
            for (int i = 0; i < 16; i++) {
                float4 v = srow[i];
                red_add_v4(dst + i * 4, v.x, v.y, v.z, v.w);
            }
        }
        __syncthreads();
    }
}

// ---------------------------------------------------------------------------
// Node update on split-bf16 HMMA:
//   h = LN1(hV + dh); dh2 = relu(h@D1+db1)@D2+db2; out = LN2(h + dh2)
// 128 nodes per block, 256 threads (8 warps: mw 0..3 rows, nw 0..1 cols)
// ---------------------------------------------------------------------------
__global__ void __launch_bounds__(256, 1)
node_mma_kernel(const float* __restrict__ hV,
                const float* __restrict__ db1g, const float* __restrict__ db2g,
                const float* __restrict__ g1g,  const float* __restrict__ be1g,
                const float* __restrict__ g2g,  const float* __restrict__ be2g,
                float* __restrict__ out) {
    extern __shared__ char smem[];
    const uint32_t sb = smem_u32(smem);
    const int tid  = threadIdx.x;
    const int wid  = tid >> 5;
    const int lane = tid & 31;
    const int mw   = wid & 3;
    const int nw   = wid >> 2;
    const int n0   = blockIdx.x * 128;

    float* s_db1 = (float*)(smem + NOFF_DB1);
    float* s_db2 = (float*)(smem + NOFF_DB2);
    float* s_g1  = (float*)(smem + NOFF_G1);
    float* s_be1 = (float*)(smem + NOFF_BE1);
    float* s_g2  = (float*)(smem + NOFF_G2);
    float* s_be2 = (float*)(smem + NOFF_BE2);
    float2* s_st = (float2*)(smem + NOFF_ST);

    // ---- stage params --------------------------------------------------------
    for (int i = tid; i < FF; i += 256) s_db1[i] = db1g[i];
    if (tid < 128) {
        s_db2[tid] = db2g[tid];
        s_g1[tid]  = g1g[tid];  s_be1[tid] = be1g[tid];
        s_g2[tid]  = g2g[tid];  s_be2[tid] = be2g[tid];
    }

    // ---- phase 1: x = hV + dh staged to fp32 scratch, row sums ---------------
    {
        const int row  = tid >> 1;
        const int half = tid & 1;
        const int grow = min(n0 + row, N_NODES - 1);
        const float4* xv = reinterpret_cast<const float4*>(hV   + (size_t)grow * HD + half * 64);
        const float4* dv = reinterpret_cast<const float4*>(g_dh + (size_t)grow * HD + half * 64);
        float sum = 0.f, sq = 0.f;
        char* stage = smem + NOFF_W + row * 528 + half * 256;
#pragma unroll
        for (int i = 0; i < 16; i++) {
            float4 a = xv[i], b = dv[i];
            a.x += b.x; a.y += b.y; a.z += b.z; a.w += b.w;
            *reinterpret_cast<float4*>(stage + i * 16) = a;
            sum += a.x + a.y + a.z + a.w;
            sq  += a.x * a.x + a.y * a.y + a.z * a.z + a.w * a.w;
        }
        sum += __shfl_xor_sync(0xffffffffu, sum, 1);
        sq  += __shfl_xor_sync(0xffffffffu, sq, 1);
        const float mean = sum * (1.f / HD);
        const float var  = sq * (1.f / HD) - mean * mean;
        const float rstd = rsqrtf(var + LN_EPS);
        __syncthreads();                    // params visible
        // normalize own data, split to hi/lo bf16
#pragma unroll
        for (int i = 0; i < 16; i++) {
            float4 a = *reinterpret_cast<float4*>(stage + i * 16);
            const int c0 = half * 64 + i * 4;
            float h0 = (a.x - mean) * rstd * s_g1[c0 + 0] + s_be1[c0 + 0];
            float h1 = (a.y - mean) * rstd * s_g1[c0 + 1] + s_be1[c0 + 1];
            float h2 = (a.z - mean) * rstd * s_g1[c0 + 2] + s_be1[c0 + 2];
            float h3 = (a.w - mean) * rstd * s_g1[c0 + 3] + s_be1[c0 + 3];
            uint32_t ha, la, hb, lb;
            split2(h0, h1, ha, la);
            split2(h2, h3, hb, lb);
            uint2 uh = make_uint2(ha, hb), ul = make_uint2(la, lb);
            *reinterpret_cast<uint2*>(smem + NOFF_XH + row * NS2 + c0 * 2) = uh;
            *reinterpret_cast<uint2*>(smem + NOFF_XL + row * NS2 + c0 * 2) = ul;
        }
    }
    __syncthreads();

    // ---- phase 2: FFN over 4 hidden chunks -----------------------------------
    float acc2[2][8][4];
#pragma unroll
    for (int i = 0; i < 2; i++)
#pragma unroll
        for (int j = 0; j < 8; j++)
#pragma unroll
            for (int q = 0; q < 4; q++) acc2[i][j][q] = 0.f;

    for (int c = 0; c < 4; c++) {
        // stage D1 chunk hi/lo: rows n = c*128..+127, 16B-chunks of 128 bf16
        {
            const uint4* d1h = reinterpret_cast<const uint4*>(g_D1Th);
            const uint4* d1l = reinterpret_cast<const uint4*>(g_D1Tl);
#pragma unroll
            for (int it = 0; it < 8; it++) {
                int idx = it * 256 + tid; int n = idx >> 4, ch = idx & 15;
                int gidx = (c * 128 + n) * 16 + ch;
                *reinterpret_cast<uint4*>(smem + NOFF_W + n * NS2 + ch * 16)         = d1h[gidx];
                *reinterpret_cast<uint4*>(smem + NOFF_W + 34816 + n * NS2 + ch * 16) = d1l[gidx];
            }
        }
        __syncthreads();

        // MMA layer 1 (split)
        float acc1[2][8][4];
        mlp_layer_split<8, true>(sb, NOFF_XH, NOFF_XL, NOFF_W, NOFF_W + 34816,
                                 lane, mw, nw, acc1);

        // epilogue: bias + relu -> split hidden
#pragma unroll
        for (int i = 0; i < 2; i++) {
            const int r = mw * 32 + i * 16 + (lane >> 2);
#pragma unroll
            for (int j = 0; j < 8; j++) {
                const int cc = nw * 64 + j * 8 + (lane & 3) * 2;
                const float b0 = s_db1[c * 128 + cc], b1 = s_db1[c * 128 + cc + 1];
                float f0 = fmaxf(acc1[i][j][0] + b0, 0.f);
                float f1 = fmaxf(acc1[i][j][1] + b1, 0.f);
                float f2 = fmaxf(acc1[i][j][2] + b0, 0.f);
                float f3 = fmaxf(acc1[i][j][3] + b1, 0.f);
                uint32_t h01, l01, h23, l23;
                split2(f0, f1, h01, l01);
                split2(f2, f3, h23, l23);
                *reinterpret_cast<uint32_t*>(smem + NOFF_HH + r * NS2 + cc * 2)       = h01;
                *reinterpret_cast<uint32_t*>(smem + NOFF_HL + r * NS2 + cc * 2)       = l01;
                *reinterpret_cast<uint32_t*>(smem + NOFF_HH + (r + 8) * NS2 + cc * 2) = h23;
                *reinterpret_cast<uint32_t*>(smem + NOFF_HL + (r + 8) * NS2 + cc * 2) = l23;
            }
        }
        __syncthreads();     // MMA1 reads of s_w done; hidden ready

        // stage D2 chunk hi/lo: rows n = 0..127, k-slice c*128..+127
        {
            const uint4* d2h = reinterpret_cast<const uint4*>(g_D2Th);
            const uint4* d2l = reinterpret_cast<const uint4*>(g_D2Tl);
#pragma unroll
            for (int it = 0; it < 8; it++) {
                int idx = it * 256 + tid; int n = idx >> 4, ch = idx & 15;
                int gidx = n * 64 + c * 16 + ch;
                *reinterpret_cast<uint4*>(smem + NOFF_W + n * NS2 + ch * 16)         = d2h[gidx];
                *reinterpret_cast<uint4*>(smem + NOFF_W + 34816 + n * NS2 + ch * 16) = d2l[gidx];
            }
        }
        __syncthreads();

        // MMA layer 2 (split, accumulate)
        mlp_layer_split<8, false>(sb, NOFF_HH, NOFF_HL, NOFF_W, NOFF_W + 34816,
                                  lane, mw, nw, acc2);
        __syncthreads();     // s_w / hidden free for next chunk
    }

    // ---- phase 3: residual + db2, LN2, store ---------------------------------
    float sums[2][2], sqs[2][2];
#pragma unroll
    for (int i = 0; i < 2; i++) { sums[i][0] = sums[i][1] = 0.f; sqs[i][0] = sqs[i][1] = 0.f; }

#pragma unroll
    for (int i = 0; i < 2; i++) {
        const int r = mw * 32 + i * 16 + (lane >> 2);
#pragma unroll
        for (int j = 0; j < 8; j++) {
            const int cc = nw * 64 + j * 8 + (lane & 3) * 2;
            const uint32_t off = r * NS2 + cc * 2;
            uint32_t xh0 = *reinterpret_cast<uint32_t*>(smem + NOFF_XH + off);
            uint32_t xl0 = *reinterpret_cast<uint32_t*>(smem + NOFF_XL + off);
            uint32_t xh1 = *reinterpret_cast<uint32_t*>(smem + NOFF_XH + off + 8 * NS2);
            uint32_t xl1 = *reinterpret_cast<uint32_t*>(smem + NOFF_XL + off + 8 * NS2);
            float v0 = acc2[i][j][0] + s_db2[cc]     + bflo(xh0) + bflo(xl0);
            float v1 = acc2[i][j][1] + s_db2[cc + 1] + bfhi(xh0) + bfhi(xl0);
            float v2 = acc2[i][j][2] + s_db2[cc]     + bflo(xh1) + bflo(xl1);
            float v3 = acc2[i][j][3] + s_db2[cc + 1] + bfhi(xh1) + bfhi(xl1);
            acc2[i][j][0] = v0; acc2[i][j][1] = v1; acc2[i][j][2] = v2; acc2[i][j][3] = v3;
            sums[i][0] += v0 + v1;           sqs[i][0] += v0 * v0 + v1 * v1;
            sums[i][1] += v2 + v3;           sqs[i][1] += v2 * v2 + v3 * v3;
        }
    }
    // reduce 64-col half sums across the 4 lanes sharing a row
#pragma unroll
    for (int i = 0; i < 2; i++)
#pragma unroll
        for (int qh = 0; qh < 2; qh++) {
            float s = sums[i][qh], q = sqs[i][qh];
            s += __shfl_xor_sync(0xffffffffu, s, 1);
            q += __shfl_xor_sync(0xffffffffu, q, 1);
            s += __shfl_xor_sync(0xffffffffu, s, 2);
            q += __shfl_xor_sync(0xffffffffu, q, 2);
            sums[i][qh] = s; sqs[i][qh] = q;
        }
    if ((lane & 3) == 0) {
#pragma unroll
        for (int i = 0; i < 2; i++)
#pragma unroll
            for (int qh = 0; qh < 2; qh++) {
                const int r = mw * 32 + i * 16 + qh * 8 + (lane >> 2);
                s_st[r * 2 + nw] = make_float2(sums[i][qh], sqs[i][qh]);
            }
    }
    __syncthreads();

    // normalize fragments into fp32 stage (reuse s_w region, stride 528B)
#pragma unroll
    for (int i = 0; i < 2; i++) {
#pragma unroll
        for (int qh = 0; qh < 2; qh++) {
            const int r = mw * 32 + i * 16 + qh * 8 + (lane >> 2);
            float2 A = s_st[r * 2 + 0], B = s_st[r * 2 + 1];
            float S = A.x + B.x, Q = A.y + B.y;
            float mean = S * (1.f / HD);
            float var  = Q * (1.f / HD) - mean * mean;
            float rstd = rsqrtf(var + LN_EPS);
#pragma unroll
            for (int j = 0; j < 8; j++) {
                const int cc = nw * 64 + j * 8 + (lane & 3) * 2;
                float v0 = acc2[i][j][qh * 2 + 0];
                float v1 = acc2[i][j][qh * 2 + 1];
                float2 o;
                o.x = (v0 - mean) * rstd * s_g2[cc]     + s_be2[cc];
                o.y = (v1 - mean) * rstd * s_g2[cc + 1] + s_be2[cc + 1];
                *reinterpret_cast<float2*>(smem + NOFF_W + r * 528 + cc * 4) = o;
            }
        }
    }
    __syncthreads();

    // coalesced store
#pragma unroll
    for (int it = 0; it < 16; it++) {
        int idx = it * 256 + tid; int r = idx >> 5, c4 = idx & 31;
        if (n0 + r < N_NODES) {
            float4 v = *reinterpret_cast<float4*>(smem + NOFF_W + r * 528 + c4 * 16);
            *reinterpret_cast<float4*>(out + (size_t)(n0 + r) * HD + c4 * 4) = v;
        }
    }
}

// ---------------------------------------------------------------------------
extern "C" void kernel_launch(void* const* d_in, const int* in_sizes, int n_in,
                              void* d_out, int out_size) {
    const float* hV    = (const float*)d_in[0];
    const float* hE    = (const float*)d_in[1];
    const int*   eidx  = (const int*)d_in[2];
    const float* W1    = (const float*)d_in[3];
    const float* b1    = (const float*)d_in[4];
    const float* W2    = (const float*)d_in[5];
    const float* b2    = (const float*)d_in[6];
    const float* W3    = (const float*)d_in[7];
    const float* b3    = (const float*)d_in[8];
    const float* D1    = (const float*)d_in[9];
    const float* db1   = (const float*)d_in[10];
    const float* D2    = (const float*)d_in[11];
    const float* db2   = (const float*)d_in[12];
    const float* g1    = (const float*)d_in[13];
    const float* beta1 = (const float*)d_in[14];
    const float* g2    = (const float*)d_in[15];
    const float* beta2 = (const float*)d_in[16];
    float*       out   = (float*)d_out;

    static int attr_set = 0;
    if (!attr_set) {
        cudaFuncSetAttribute(edge_hmma_kernel,
                             cudaFuncAttributeMaxDynamicSharedMemorySize, SMEM_TOTAL);
        cudaFuncSetAttribute(node_mma_kernel,
                             cudaFuncAttributeMaxDynamicSharedMemorySize, NSMEM_TOTAL);
        attr_set = 1;
    }

    prep_weights_kernel<<<512, 128>>>(W1, W2, W3, D1, D2);
    zero_dh_kernel<<<1024, 256>>>();
    edge_hmma_kernel<<<148, 256, SMEM_TOTAL>>>(hE, eidx, b1, b2, b3);
    node_mma_kernel<<<NODE_TILES, 256, NSMEM_TOTAL>>>(hV, db1, db2,
                                                      g1, beta1, g2, beta2, out);
}

// round 10
// speedup vs baseline: 4.6911x; 1.1171x over previous
#include <cuda_runtime.h>
#include <cuda_bf16.h>
#include <stdint.h>
#include <math.h>

#define N_NODES 100000
#define N_EDGES 800000
#define HD      128            // hidden dim H
#define K1      256            // H + IN
#define FF      512            // 4*H
#define INV_SCALE (1.0f/30.0f)
#define LN_EPS  1e-5f

#define ET 128                 // edges per tile (edge kernel)
#define N_TILES (N_EDGES / ET) // 6250
#define NODE_TILES ((N_NODES + 127) / 128)   // 782

// ---------------------------------------------------------------------------
// device globals (no cudaMalloc allowed)
// ---------------------------------------------------------------------------
__device__ float          g_dh[(size_t)N_NODES * HD];
__device__ __nv_bfloat16  g_WT1[HD * K1];   // W1^T  [n=128][k=256] bf16
__device__ __nv_bfloat16  g_WT2[HD * HD];   // W2^T  [128][128] bf16
__device__ __nv_bfloat16  g_WT3[HD * HD];   // W3^T  [128][128] bf16
__device__ __nv_bfloat16  g_D1Th[FF * HD];  // D1^T hi  [512][128]
__device__ __nv_bfloat16  g_D1Tl[FF * HD];  // D1^T lo
__device__ __nv_bfloat16  g_D2Th[HD * FF];  // D2^T hi  [128][512]
__device__ __nv_bfloat16  g_D2Tl[HD * FF];  // D2^T lo

// ---------------------------------------------------------------------------
// EDGE kernel SMEM layout (bytes); strides padded for conflict-free ldmatrix
// ---------------------------------------------------------------------------
#define AS1   528
#define WS1   528
#define WS2   272
#define OFF_A    0
#define OFF_W1   67584
#define OFF_W2   135168
#define OFF_W3   169984
#define OFF_B1   204800
#define OFF_B2   205312
#define OFF_B3   205824
#define OFF_SRC  206336        // 2 x 512B (double-buffered src indices)
#define SMEM_TOTAL 207360

// ---------------------------------------------------------------------------
// NODE kernel SMEM layout (bytes); bf16 tiles use stride 272
// ---------------------------------------------------------------------------
#define NS2 272
#define NOFF_XH  0            // h hi   [128][128] bf16  34816
#define NOFF_XL  34816        // h lo
#define NOFF_HH  69632        // hidden hi
#define NOFF_HL  104448       // hidden lo
#define NOFF_W   139264       // weight chunk hi(+0)/lo(+34816); reused fp32 stage
#define NOFF_DB1 208896       // 512 f
#define NOFF_DB2 210944
#define NOFF_G1  211456
#define NOFF_BE1 211968
#define NOFF_G2  212480
#define NOFF_BE2 212992
#define NOFF_ST  213504       // stats float2 [128][2]
#define NSMEM_TOTAL 215552

// ---------------------------------------------------------------------------
// PTX helpers — ONLY non-'a' instructions (ldmatrix / mma.sync / red.global)
// ---------------------------------------------------------------------------
__device__ __forceinline__ uint32_t smem_u32(const void* p) {
    uint32_t a;
    asm("{ .reg .u64 t; cvta.to.shared.u64 t, %1; cvt.u32.u64 %0, t; }" : "=r"(a) : "l"(p));
    return a;
}
__device__ __forceinline__ void ldsm_x4(uint32_t addr, uint32_t& r0, uint32_t& r1,
                                        uint32_t& r2, uint32_t& r3) {
    asm volatile("ldmatrix.sync.aligned.m8n8.x4.shared.b16 {%0,%1,%2,%3}, [%4];"
                 : "=r"(r0), "=r"(r1), "=r"(r2), "=r"(r3) : "r"(addr));
}
__device__ __forceinline__ void mma_16816(float c[4], uint32_t a0, uint32_t a1,
                                          uint32_t a2, uint32_t a3,
                                          uint32_t b0, uint32_t b1) {
    asm volatile("mma.sync.aligned.m16n8k16.row.col.f32.bf16.bf16.f32 "
                 "{%0,%1,%2,%3}, {%4,%5,%6,%7}, {%8,%9}, {%0,%1,%2,%3};"
                 : "+f"(c[0]), "+f"(c[1]), "+f"(c[2]), "+f"(c[3])
                 : "r"(a0), "r"(a1), "r"(a2), "r"(a3), "r"(b0), "r"(b1));
}
// pack: low half = first arg
__device__ __forceinline__ uint32_t pk2(float lo, float hi) {
    uint32_t r;
    asm("cvt.rn.bf16x2.f32 %0, %1, %2;" : "=r"(r) : "f"(hi), "f"(lo));
    return r;
}
__device__ __forceinline__ float bflo(uint32_t u) {
    __nv_bfloat162 t = *reinterpret_cast<__nv_bfloat162*>(&u);
    return __bfloat162float(t.x);
}
__device__ __forceinline__ float bfhi(uint32_t u) {
    __nv_bfloat162 t = *reinterpret_cast<__nv_bfloat162*>(&u);
    return __bfloat162float(t.y);
}
__device__ __forceinline__ void split2(float a, float b, uint32_t& h, uint32_t& l) {
    h = pk2(a, b);
    l = pk2(a - bflo(h), b - bfhi(h));
}
__device__ __forceinline__ void red_add_v4(float* p, float a, float b, float c, float d) {
    asm volatile("red.global.add.v4.f32 [%0], {%1, %2, %3, %4};"
                 :: "l"(p), "f"(a), "f"(b), "f"(c), "f"(d) : "memory");
}

// ---------------------------------------------------------------------------
// single-bf16 MLP layer (edge): acc = A[128xK] @ W[128xK]^T
// B fragments fetched pairwise (j, j+1) via ldmatrix.x4.
// ---------------------------------------------------------------------------
template <int KSTEPS, int ASTRIDE, int WSTRIDE>
__device__ __forceinline__ void mlp_layer(uint32_t sb, int Aoff, int Woff,
                                          int lane, int mw, int nw,
                                          float acc[2][8][4]) {
#pragma unroll
    for (int i = 0; i < 2; i++)
#pragma unroll
        for (int j = 0; j < 8; j++)
#pragma unroll
            for (int q = 0; q < 4; q++) acc[i][j][q] = 0.f;

    const uint32_t aBase = sb + Aoff + (mw * 32 + (lane & 15)) * ASTRIDE + ((lane >> 4) << 4);
    // x4 B: m0,m1 = rows j*8..+7 halves 0,1 ; m2,m3 = rows j*8+8..+15 halves 0,1
    const uint32_t bBase = sb + Woff
        + (nw * 64 + (lane & 7) + ((lane >> 4) << 3)) * WSTRIDE
        + (((lane >> 3) & 1) << 4);

#pragma unroll
    for (int ks = 0; ks < KSTEPS; ks++) {
        const int k0b = ks * 32;
        uint32_t a0, a1, a2, a3, a4, a5, a6, a7;
        ldsm_x4(aBase + k0b, a0, a1, a2, a3);
        ldsm_x4(aBase + 16 * ASTRIDE + k0b, a4, a5, a6, a7);
#pragma unroll
        for (int p = 0; p < 4; p++) {
            uint32_t b0, b1, b2, b3;
            ldsm_x4(bBase + p * 16 * WSTRIDE + k0b, b0, b1, b2, b3);
            mma_16816(acc[0][2 * p],     a0, a1, a2, a3, b0, b1);
            mma_16816(acc[1][2 * p],     a4, a5, a6, a7, b0, b1);
            mma_16816(acc[0][2 * p + 1], a0, a1, a2, a3, b2, b3);
            mma_16816(acc[1][2 * p + 1], a4, a5, a6, a7, b2, b3);
        }
    }
}

// split (hi/lo) MLP layer (node): acc (+)= Ah@Wh + Ah@Wl + Al@Wh
template <int KSTEPS, bool CLEAR>
__device__ __forceinline__ void mlp_layer_split(uint32_t sb, int AHoff, int ALoff,
                                                int WHoff, int WLoff,
                                                int lane, int mw, int nw,
                                                float acc[2][8][4]) {
    if (CLEAR) {
#pragma unroll
        for (int i = 0; i < 2; i++)
#pragma unroll
            for (int j = 0; j < 8; j++)
#pragma unroll
                for (int q = 0; q < 4; q++) acc[i][j][q] = 0.f;
    }
    const uint32_t rb = (mw * 32 + (lane & 15)) * NS2 + ((lane >> 4) << 4);
    const uint32_t ahB = sb + AHoff + rb;
    const uint32_t alB = sb + ALoff + rb;
    const uint32_t wb = (nw * 64 + (lane & 7) + ((lane >> 4) << 3)) * NS2
                      + (((lane >> 3) & 1) << 4);
    const uint32_t whB = sb + WHoff + wb;
    const uint32_t wlB = sb + WLoff + wb;

#pragma unroll
    for (int ks = 0; ks < KSTEPS; ks++) {
        const int k0b = ks * 32;
        uint32_t h0, h1, h2, h3, h4, h5, h6, h7;
        uint32_t l0, l1, l2, l3, l4, l5, l6, l7;
        ldsm_x4(ahB + k0b, h0, h1, h2, h3);
        ldsm_x4(ahB + 16 * NS2 + k0b, h4, h5, h6, h7);
        ldsm_x4(alB + k0b, l0, l1, l2, l3);
        ldsm_x4(alB + 16 * NS2 + k0b, l4, l5, l6, l7);
#pragma unroll
        for (int p = 0; p < 4; p++) {
            uint32_t wh0, wh1, wh2, wh3, wl0, wl1, wl2, wl3;
            ldsm_x4(whB + p * 16 * NS2 + k0b, wh0, wh1, wh2, wh3);
            ldsm_x4(wlB + p * 16 * NS2 + k0b, wl0, wl1, wl2, wl3);
            mma_16816(acc[0][2 * p], h0, h1, h2, h3, wh0, wh1);
            mma_16816(acc[0][2 * p], h0, h1, h2, h3, wl0, wl1);
            mma_16816(acc[0][2 * p], l0, l1, l2, l3, wh0, wh1);
            mma_16816(acc[1][2 * p], h4, h5, h6, h7, wh0, wh1);
            mma_16816(acc[1][2 * p], h4, h5, h6, h7, wl0, wl1);
            mma_16816(acc[1][2 * p], l4, l5, l6, l7, wh0, wh1);
            mma_16816(acc[0][2 * p + 1], h0, h1, h2, h3, wh2, wh3);
            mma_16816(acc[0][2 * p + 1], h0, h1, h2, h3, wl2, wl3);
            mma_16816(acc[0][2 * p + 1], l0, l1, l2, l3, wh2, wh3);
            mma_16816(acc[1][2 * p + 1], h4, h5, h6, h7, wh2, wh3);
            mma_16816(acc[1][2 * p + 1], h4, h5, h6, h7, wl2, wl3);
            mma_16816(acc[1][2 * p + 1], l4, l5, l6, l7, wh2, wh3);
        }
    }
}

// bias + relu -> bf16, write into edge A/mid region (stride AS1)
__device__ __forceinline__ void epi_relu_pack(char* smem, const float* bias,
                                              int lane, int mw, int nw,
                                              float acc[2][8][4]) {
#pragma unroll
    for (int i = 0; i < 2; i++) {
        const int r = mw * 32 + i * 16 + (lane >> 2);
#pragma unroll
        for (int j = 0; j < 8; j++) {
            const int c = nw * 64 + j * 8 + (lane & 3) * 2;
            const float bc0 = bias[c], bc1 = bias[c + 1];
            float f0 = fmaxf(acc[i][j][0] + bc0, 0.f);
            float f1 = fmaxf(acc[i][j][1] + bc1, 0.f);
            float f2 = fmaxf(acc[i][j][2] + bc0, 0.f);
            float f3 = fmaxf(acc[i][j][3] + bc1, 0.f);
            *reinterpret_cast<uint32_t*>(smem + OFF_A + r * AS1 + c * 2)       = pk2(f0, f1);
            *reinterpret_cast<uint32_t*>(smem + OFF_A + (r + 8) * AS1 + c * 2) = pk2(f2, f3);
        }
    }
}

// ---------------------------------------------------------------------------
// prep: transpose + bf16-convert all weights (edge single, node hi/lo split)
// ---------------------------------------------------------------------------
__global__ void prep_weights_kernel(const float* __restrict__ W1,
                                    const float* __restrict__ W2,
                                    const float* __restrict__ W3,
                                    const float* __restrict__ D1,
                                    const float* __restrict__ D2) {
    int n = blockIdx.x;            // 0..511
    int t = threadIdx.x;           // 128 threads
    {
        float v = D1[t * FF + n];
        __nv_bfloat16 h = __float2bfloat16(v);
        g_D1Th[n * HD + t] = h;
        g_D1Tl[n * HD + t] = __float2bfloat16(v - __bfloat162float(h));
    }
    if (n < HD) {
        for (int k = t; k < K1; k += blockDim.x)
            g_WT1[n * K1 + k] = __float2bfloat16(W1[k * HD + n]);
        for (int k = t; k < HD; k += blockDim.x) {
            g_WT2[n * HD + k] = __float2bfloat16(W2[k * HD + n]);
            g_WT3[n * HD + k] = __float2bfloat16(W3[k * HD + n]);
        }
        for (int k = t; k < FF; k += blockDim.x) {
            float v = D2[k * HD + n];
            __nv_bfloat16 h = __float2bfloat16(v);
            g_D2Th[n * FF + k] = h;
            g_D2Tl[n * FF + k] = __float2bfloat16(v - __bfloat162float(h));
        }
    }
}

__global__ void zero_dh_kernel() {
    size_t n4 = (size_t)N_NODES * HD / 4;
    float4 z = make_float4(0.f, 0.f, 0.f, 0.f);
    float4* p = reinterpret_cast<float4*>(g_dh);
    for (size_t i = (size_t)blockIdx.x * blockDim.x + threadIdx.x; i < n4;
         i += (size_t)gridDim.x * blockDim.x)
        p[i] = z;
}

// ---------------------------------------------------------------------------
// Edge MLP on warp-level bf16 HMMA. Persistent: grid=148, 256 threads.
// Register-direct scatter overlapped with next-tile A staging.
// ---------------------------------------------------------------------------
__global__ void __launch_bounds__(256, 1)
edge_hmma_kernel(const float* __restrict__ hE,
                 const int* __restrict__ eidx,
                 const float* __restrict__ b1,
                 const float* __restrict__ b2,
                 const float* __restrict__ b3) {
    extern __shared__ char smem[];
    const uint32_t sb = smem_u32(smem);
    const int tid  = threadIdx.x;
    const int wid  = tid >> 5;
    const int lane = tid & 31;
    const int mw   = wid & 3;
    const int nw   = wid >> 2;

    // ---- stage weights ------------------------------------------------------
    {
        const uint4* w1g = reinterpret_cast<const uint4*>(g_WT1);
#pragma unroll
        for (int i = 0; i < 16; i++) {
            int idx = i * 256 + tid; int n = idx >> 5, ch = idx & 31;
            *reinterpret_cast<uint4*>(smem + OFF_W1 + n * WS1 + ch * 16) = w1g[n * 32 + ch];
        }
        const uint4* w2g = reinterpret_cast<const uint4*>(g_WT2);
        const uint4* w3g = reinterpret_cast<const uint4*>(g_WT3);
#pragma unroll
        for (int i = 0; i < 8; i++) {
            int idx = i * 256 + tid; int n = idx >> 4, ch = idx & 15;
            *reinterpret_cast<uint4*>(smem + OFF_W2 + n * WS2 + ch * 16) = w2g[n * 16 + ch];
            *reinterpret_cast<uint4*>(smem + OFF_W3 + n * WS2 + ch * 16) = w3g[n * 16 + ch];
        }
        if (tid < 128) {
            ((float*)(smem + OFF_B1))[tid] = b1[tid];
            ((float*)(smem + OFF_B2))[tid] = b2[tid];
            ((float*)(smem + OFF_B3))[tid] = b3[tid];
        }
    }

    const float* bias1 = (const float*)(smem + OFF_B1);
    const float* bias2 = (const float*)(smem + OFF_B2);
    const float* bias3 = (const float*)(smem + OFF_B3);
    int* srcArr = (int*)(smem + OFF_SRC);

    // ---- stage first tile's A + src ----------------------------------------
    {
        const int e0 = blockIdx.x * ET;
        const float4* gE4 = reinterpret_cast<const float4*>(hE) + (size_t)e0 * 64;
#pragma unroll
        for (int i = 0; i < 16; i++) {
            int idx = i * 256 + tid; int r = idx >> 5, ch = idx & 31;
            float4 fa = gE4[(size_t)r * 64 + ch * 2];
            float4 fb = gE4[(size_t)r * 64 + ch * 2 + 1];
            uint4 u;
            u.x = pk2(fa.x, fa.y); u.y = pk2(fa.z, fa.w);
            u.z = pk2(fb.x, fb.y); u.w = pk2(fb.z, fb.w);
            *reinterpret_cast<uint4*>(smem + OFF_A + r * AS1 + ch * 16) = u;
        }
        if (tid < 128) srcArr[tid] = eidx[e0 + tid];
    }
    __syncthreads();

    float acc[2][8][4];
    int buf = 0;

    for (int tile = blockIdx.x; tile < N_TILES; tile += gridDim.x) {
        mlp_layer<16, AS1, WS1>(sb, OFF_A, OFF_W1, lane, mw, nw, acc);
        __syncthreads();
        epi_relu_pack(smem, bias1, lane, mw, nw, acc);
        __syncthreads();

        mlp_layer<8, AS1, WS2>(sb, OFF_A, OFF_W2, lane, mw, nw, acc);
        __syncthreads();
        epi_relu_pack(smem, bias2, lane, mw, nw, acc);
        __syncthreads();

        mlp_layer<8, AS1, WS2>(sb, OFF_A, OFF_W3, lane, mw, nw, acc);
        __syncthreads();        // A region + srcArr[buf] now free to repurpose

        // ---- prefetch next tile's A + src (overlaps scatter below) ----------
        const int ntile = tile + (int)gridDim.x;
        if (ntile < N_TILES) {
            const int e0 = ntile * ET;
            const float4* gE4 = reinterpret_cast<const float4*>(hE) + (size_t)e0 * 64;
#pragma unroll
            for (int i = 0; i < 16; i++) {
                int idx = i * 256 + tid; int r = idx >> 5, ch = idx & 31;
                float4 fa = gE4[(size_t)r * 64 + ch * 2];
                float4 fb = gE4[(size_t)r * 64 + ch * 2 + 1];
                uint4 u;
                u.x = pk2(fa.x, fa.y); u.y = pk2(fa.z, fa.w);
                u.z = pk2(fb.x, fb.y); u.w = pk2(fb.z, fb.w);
                *reinterpret_cast<uint4*>(smem + OFF_A + r * AS1 + ch * 16) = u;
            }
            if (tid < 128) srcArr[(buf ^ 1) * 128 + tid] = eidx[e0 + tid];
        }

        // ---- register-direct scatter: (acc + b3)/SCALE -> red.v4 ------------
        {
            const bool even = (lane & 1) == 0;
            const int cb   = nw * 64 + ((lane >> 1) & 1) * 4;   // 4-col base
            const int r0a  = mw * 32 + (lane >> 2) + (even ? 0 : 8);
            const int src0 = srcArr[buf * 128 + r0a];
            const int src1 = srcArr[buf * 128 + r0a + 16];
            float* dst0 = g_dh + (size_t)src0 * HD;
            float* dst1 = g_dh + (size_t)src1 * HD;
#pragma unroll
            for (int i = 0; i < 2; i++) {
                float* dst = i ? dst1 : dst0;
#pragma unroll
                for (int j = 0; j < 8; j++) {
                    const int c = nw * 64 + j * 8 + (lane & 3) * 2;
                    float v0 = (acc[i][j][0] + bias3[c])     * INV_SCALE;
                    float v1 = (acc[i][j][1] + bias3[c + 1]) * INV_SCALE;
                    float v2 = (acc[i][j][2] + bias3[c])     * INV_SCALE;
                    float v3 = (acc[i][j][3] + bias3[c + 1]) * INV_SCALE;
                    float o0 = __shfl_xor_sync(0xffffffffu, v0, 1);
                    float o1 = __shfl_xor_sync(0xffffffffu, v1, 1);
                    float o2 = __shfl_xor_sync(0xffffffffu, v2, 1);
                    float o3 = __shfl_xor_sync(0xffffffffu, v3, 1);
                    if (even) red_add_v4(dst + j * 8 + cb - nw * 64 + nw * 64, v0, v1, o0, o1);
                    else      red_add_v4(dst + j * 8 + cb - nw * 64 + nw * 64, o2, o3, v2, v3);
                }
            }
        }
        __syncthreads();
        buf ^= 1;
    }
}

// ---------------------------------------------------------------------------
// Node update on split-bf16 HMMA (R8 winner + paired-x4 weight ldsm)
// ---------------------------------------------------------------------------
__global__ void __launch_bounds__(256, 1)
node_mma_kernel(const float* __restrict__ hV,
                const float* __restrict__ db1g, const float* __restrict__ db2g,
                const float* __restrict__ g1g,  const float* __restrict__ be1g,
                const float* __restrict__ g2g,  const float* __restrict__ be2g,
                float* __restrict__ out) {
    extern __shared__ char smem[];
    const uint32_t sb = smem_u32(smem);
    const int tid  = threadIdx.x;
    const int lane = tid & 31;
    const int wid  = tid >> 5;
    const int mw   = wid & 3;
    const int nw   = wid >> 2;
    const int n0   = blockIdx.x * 128;

    float* s_db1 = (float*)(smem + NOFF_DB1);
    float* s_db2 = (float*)(smem + NOFF_DB2);
    float* s_g1  = (float*)(smem + NOFF_G1);
    float* s_be1 = (float*)(smem + NOFF_BE1);
    float* s_g2  = (float*)(smem + NOFF_G2);
    float* s_be2 = (float*)(smem + NOFF_BE2);
    float2* s_st = (float2*)(smem + NOFF_ST);

    for (int i = tid; i < FF; i += 256) s_db1[i] = db1g[i];
    if (tid < 128) {
        s_db2[tid] = db2g[tid];
        s_g1[tid]  = g1g[tid];  s_be1[tid] = be1g[tid];
        s_g2[tid]  = g2g[tid];  s_be2[tid] = be2g[tid];
    }

    // ---- phase 1: x = hV + dh ; LN1 ; split hi/lo ---------------------------
    {
        const int row  = tid >> 1;
        const int half = tid & 1;
        const int grow = min(n0 + row, N_NODES - 1);
        const float4* xv = reinterpret_cast<const float4*>(hV   + (size_t)grow * HD + half * 64);
        const float4* dv = reinterpret_cast<const float4*>(g_dh + (size_t)grow * HD + half * 64);
        float sum = 0.f, sq = 0.f;
        char* stage = smem + NOFF_W + row * 528 + half * 256;
#pragma unroll
        for (int i = 0; i < 16; i++) {
            float4 a = xv[i], b = dv[i];
            a.x += b.x; a.y += b.y; a.z += b.z; a.w += b.w;
            *reinterpret_cast<float4*>(stage + i * 16) = a;
            sum += a.x + a.y + a.z + a.w;
            sq  += a.x * a.x + a.y * a.y + a.z * a.z + a.w * a.w;
        }
        sum += __shfl_xor_sync(0xffffffffu, sum, 1);
        sq  += __shfl_xor_sync(0xffffffffu, sq, 1);
        const float mean = sum * (1.f / HD);
        const float var  = sq * (1.f / HD) - mean * mean;
        const float rstd = rsqrtf(var + LN_EPS);
        __syncthreads();
#pragma unroll
        for (int i = 0; i < 16; i++) {
            float4 a = *reinterpret_cast<float4*>(stage + i * 16);
            const int c0 = half * 64 + i * 4;
            float h0 = (a.x - mean) * rstd * s_g1[c0 + 0] + s_be1[c0 + 0];
            float h1 = (a.y - mean) * rstd * s_g1[c0 + 1] + s_be1[c0 + 1];
            float h2 = (a.z - mean) * rstd * s_g1[c0 + 2] + s_be1[c0 + 2];
            float h3 = (a.w - mean) * rstd * s_g1[c0 + 3] + s_be1[c0 + 3];
            uint32_t ha, la, hb, lb;
            split2(h0, h1, ha, la);
            split2(h2, h3, hb, lb);
            *reinterpret_cast<uint2*>(smem + NOFF_XH + row * NS2 + c0 * 2) = make_uint2(ha, hb);
            *reinterpret_cast<uint2*>(smem + NOFF_XL + row * NS2 + c0 * 2) = make_uint2(la, lb);
        }
    }
    __syncthreads();

    // ---- phase 2: FFN over 4 hidden chunks ----------------------------------
    float acc2[2][8][4];
#pragma unroll
    for (int i = 0; i < 2; i++)
#pragma unroll
        for (int j = 0; j < 8; j++)
#pragma unroll
            for (int q = 0; q < 4; q++) acc2[i][j][q] = 0.f;

    for (int c = 0; c < 4; c++) {
        {
            const uint4* d1h = reinterpret_cast<const uint4*>(g_D1Th);
            const uint4* d1l = reinterpret_cast<const uint4*>(g_D1Tl);
#pragma unroll
            for (int it = 0; it < 8; it++) {
                int idx = it * 256 + tid; int n = idx >> 4, ch = idx & 15;
                int gidx = (c * 128 + n) * 16 + ch;
                *reinterpret_cast<uint4*>(smem + NOFF_W + n * NS2 + ch * 16)         = d1h[gidx];
                *reinterpret_cast<uint4*>(smem + NOFF_W + 34816 + n * NS2 + ch * 16) = d1l[gidx];
            }
        }
        __syncthreads();

        float acc1[2][8][4];
        mlp_layer_split<8, true>(sb, NOFF_XH, NOFF_XL, NOFF_W, NOFF_W + 34816,
                                 lane, mw, nw, acc1);

#pragma unroll
        for (int i = 0; i < 2; i++) {
            const int r = mw * 32 + i * 16 + (lane >> 2);
#pragma unroll
            for (int j = 0; j < 8; j++) {
                const int cc = nw * 64 + j * 8 + (lane & 3) * 2;
                const float b0 = s_db1[c * 128 + cc], b1 = s_db1[c * 128 + cc + 1];
                float f0 = fmaxf(acc1[i][j][0] + b0, 0.f);
                float f1 = fmaxf(acc1[i][j][1] + b1, 0.f);
                float f2 = fmaxf(acc1[i][j][2] + b0, 0.f);
                float f3 = fmaxf(acc1[i][j][3] + b1, 0.f);
                uint32_t h01, l01, h23, l23;
                split2(f0, f1, h01, l01);
                split2(f2, f3, h23, l23);
                *reinterpret_cast<uint32_t*>(smem + NOFF_HH + r * NS2 + cc * 2)       = h01;
                *reinterpret_cast<uint32_t*>(smem + NOFF_HL + r * NS2 + cc * 2)       = l01;
                *reinterpret_cast<uint32_t*>(smem + NOFF_HH + (r + 8) * NS2 + cc * 2) = h23;
                *reinterpret_cast<uint32_t*>(smem + NOFF_HL + (r + 8) * NS2 + cc * 2) = l23;
            }
        }
        __syncthreads();

        {
            const uint4* d2h = reinterpret_cast<const uint4*>(g_D2Th);
            const uint4* d2l = reinterpret_cast<const uint4*>(g_D2Tl);
#pragma unroll
            for (int it = 0; it < 8; it++) {
                int idx = it * 256 + tid; int n = idx >> 4, ch = idx & 15;
                int gidx = n * 64 + c * 16 + ch;
                *reinterpret_cast<uint4*>(smem + NOFF_W + n * NS2 + ch * 16)         = d2h[gidx];
                *reinterpret_cast<uint4*>(smem + NOFF_W + 34816 + n * NS2 + ch * 16) = d2l[gidx];
            }
        }
        __syncthreads();

        mlp_layer_split<8, false>(sb, NOFF_HH, NOFF_HL, NOFF_W, NOFF_W + 34816,
                                  lane, mw, nw, acc2);
        __syncthreads();
    }

    // ---- phase 3: residual + db2, LN2, store --------------------------------
    float sums[2][2], sqs[2][2];
#pragma unroll
    for (int i = 0; i < 2; i++) { sums[i][0] = sums[i][1] = 0.f; sqs[i][0] = sqs[i][1] = 0.f; }

#pragma unroll
    for (int i = 0; i < 2; i++) {
        const int r = mw * 32 + i * 16 + (lane >> 2);
#pragma unroll
        for (int j = 0; j < 8; j++) {
            const int cc = nw * 64 + j * 8 + (lane & 3) * 2;
            const uint32_t off = r * NS2 + cc * 2;
            uint32_t xh0 = *reinterpret_cast<uint32_t*>(smem + NOFF_XH + off);
            uint32_t xl0 = *reinterpret_cast<uint32_t*>(smem + NOFF_XL + off);
            uint32_t xh1 = *reinterpret_cast<uint32_t*>(smem + NOFF_XH + off + 8 * NS2);
            uint32_t xl1 = *reinterpret_cast<uint32_t*>(smem + NOFF_XL + off + 8 * NS2);
            float v0 = acc2[i][j][0] + s_db2[cc]     + bflo(xh0) + bflo(xl0);
            float v1 = acc2[i][j][1] + s_db2[cc + 1] + bfhi(xh0) + bfhi(xl0);
            float v2 = acc2[i][j][2] + s_db2[cc]     + bflo(xh1) + bflo(xl1);
            float v3 = acc2[i][j][3] + s_db2[cc + 1] + bfhi(xh1) + bfhi(xl1);
            acc2[i][j][0] = v0; acc2[i][j][1] = v1; acc2[i][j][2] = v2; acc2[i][j][3] = v3;
            sums[i][0] += v0 + v1;           sqs[i][0] += v0 * v0 + v1 * v1;
            sums[i][1] += v2 + v3;           sqs[i][1] += v2 * v2 + v3 * v3;
        }
    }
#pragma unroll
    for (int i = 0; i < 2; i++)
#pragma unroll
        for (int qh = 0; qh < 2; qh++) {
            float s = sums[i][qh], q = sqs[i][qh];
            s += __shfl_xor_sync(0xffffffffu, s, 1);
            q += __shfl_xor_sync(0xffffffffu, q, 1);
            s += __shfl_xor_sync(0xffffffffu, s, 2);
            q += __shfl_xor_sync(0xffffffffu, q, 2);
            sums[i][qh] = s; sqs[i][qh] = q;
        }
    if ((lane & 3) == 0) {
#pragma unroll
        for (int i = 0; i < 2; i++)
#pragma unroll
            for (int qh = 0; qh < 2; qh++) {
                const int r = mw * 32 + i * 16 + qh * 8 + (lane >> 2);
                s_st[r * 2 + nw] = make_float2(sums[i][qh], sqs[i][qh]);
            }
    }
    __syncthreads();

#pragma unroll
    for (int i = 0; i < 2; i++) {
#pragma unroll
        for (int qh = 0; qh < 2; qh++) {
            const int r = mw * 32 + i * 16 + qh * 8 + (lane >> 2);
            float2 A = s_st[r * 2 + 0], B = s_st[r * 2 + 1];
            float S = A.x + B.x, Q = A.y + B.y;
            float mean = S * (1.f / HD);
            float var  = Q * (1.f / HD) - mean * mean;
            float rstd = rsqrtf(var + LN_EPS);
#pragma unroll
            for (int j = 0; j < 8; j++) {
                const int cc = nw * 64 + j * 8 + (lane & 3) * 2;
                float v0 = acc2[i][j][qh * 2 + 0];
                float v1 = acc2[i][j][qh * 2 + 1];
                float2 o;
                o.x = (v0 - mean) * rstd * s_g2[cc]     + s_be2[cc];
                o.y = (v1 - mean) * rstd * s_g2[cc + 1] + s_be2[cc + 1];
                *reinterpret_cast<float2*>(smem + NOFF_W + r * 528 + cc * 4) = o;
            }
        }
    }
    __syncthreads();

#pragma unroll
    for (int it = 0; it < 16; it++) {
        int idx = it * 256 + tid; int r = idx >> 5, c4 = idx & 31;
        if (n0 + r < N_NODES) {
            float4 v = *reinterpret_cast<float4*>(smem + NOFF_W + r * 528 + c4 * 16);
            *reinterpret_cast<float4*>(out + (size_t)(n0 + r) * HD + c4 * 4) = v;
        }
    }
}

// ---------------------------------------------------------------------------
extern "C" void kernel_launch(void* const* d_in, const int* in_sizes, int n_in,
                              void* d_out, int out_size) {
    const float* hV    = (const float*)d_in[0];
    const float* hE    = (const float*)d_in[1];
    const int*   eidx  = (const int*)d_in[2];
    const float* W1    = (const float*)d_in[3];
    const float* b1    = (const float*)d_in[4];
    const float* W2    = (const float*)d_in[5];
    const float* b2    = (const float*)d_in[6];
    const float* W3    = (const float*)d_in[7];
    const float* b3    = (const float*)d_in[8];
    const float* D1    = (const float*)d_in[9];
    const float* db1   = (const float*)d_in[10];
    const float* D2    = (const float*)d_in[11];
    const float* db2   = (const float*)d_in[12];
    const float* g1    = (const float*)d_in[13];
    const float* beta1 = (const float*)d_in[14];
    const float* g2    = (const float*)d_in[15];
    const float* beta2 = (const float*)d_in[16];
    float*       out   = (float*)d_out;

    static int attr_set = 0;
    if (!attr_set) {
        cudaFuncSetAttribute(edge_hmma_kernel,
                             cudaFuncAttributeMaxDynamicSharedMemorySize, SMEM_TOTAL);
        cudaFuncSetAttribute(node_mma_kernel,
                             cudaFuncAttributeMaxDynamicSharedMemorySize, NSMEM_TOTAL);
        attr_set = 1;
    }

    prep_weights_kernel<<<512, 128>>>(W1, W2, W3, D1, D2);
    zero_dh_kernel<<<1024, 256>>>();
    edge_hmma_kernel<<<148, 256, SMEM_TOTAL>>>(hE, eidx, b1, b2, b3);
    node_mma_kernel<<<NODE_TILES, 256, NSMEM_TOTAL>>>(hV, db1, db2,
                                                      g1, beta1, g2, beta2, out);
}